// round 1
// baseline (speedup 1.0000x reference)
#include <cuda_runtime.h>
#include <cuda_bf16.h>

#define BB 4
#define SS 1024
#define DD 1024
#define HH 16
#define DKK 64
#define DVV 32
#define BH (BB*HH)          // 64
#define MM (BB*SS)          // 4096
#define CDIM (HH*DVV)       // 512

// Scratch (device globals — no allocation in kernel_launch)
__device__ float g_q[BH*SS*DKK];      // [B,H,S,DK]
__device__ float g_k[BH*SS*DKK];
__device__ float g_v[BH*SS*DVV];
__device__ float g_concat[MM*CDIM];   // [B,S,H*DV]

// ---------------------------------------------------------------------------
// Kernel 1: fused QKV projection.
//  out[h][m][n] = x[m][:] @ W*[h][:][n] + b*, with n in [0,160):
//  [0,64)->Q, [64,128)->K, [128,160)->V
//  Tiled GEMM: BM=128, BN=32, BK=16, 256 threads, 8x2 microtile per thread.
// grid (32, 5, 16)
// ---------------------------------------------------------------------------
__global__ void proj_kernel(const float* __restrict__ x,
                            const float* __restrict__ Wq, const float* __restrict__ bq,
                            const float* __restrict__ Wk, const float* __restrict__ bk,
                            const float* __restrict__ Wv, const float* __restrict__ bv)
{
    __shared__ float As[128*16];
    __shared__ float Bs[16*32];
    const int h  = blockIdx.z;
    const int m0 = blockIdx.x * 128;
    const int n0 = blockIdx.y * 32;
    const int tid = threadIdx.x;
    const int tn = tid & 15;   // 16 col groups (2 cols each)
    const int tm = tid >> 4;   // 16 row groups (8 rows each)

    float acc[8][2];
    #pragma unroll
    for (int i = 0; i < 8; i++) { acc[i][0] = 0.f; acc[i][1] = 0.f; }

    for (int k0 = 0; k0 < DD; k0 += 16) {
        #pragma unroll
        for (int i = 0; i < 8; i++) {
            int t = tid + i * 256;
            As[t] = x[(m0 + (t >> 4)) * DD + k0 + (t & 15)];
        }
        #pragma unroll
        for (int i = 0; i < 2; i++) {
            int t = tid + i * 256;
            int dd = k0 + (t >> 5);
            int gn = n0 + (t & 31);
            float w;
            if (gn < DKK)            w = Wq[(h * DD + dd) * DKK + gn];
            else if (gn < 2 * DKK)   w = Wk[(h * DD + dd) * DKK + (gn - DKK)];
            else                     w = Wv[(h * DD + dd) * DVV + (gn - 2 * DKK)];
            Bs[t] = w;
        }
        __syncthreads();
        #pragma unroll
        for (int kk = 0; kk < 16; kk++) {
            float a[8], b0, b1;
            #pragma unroll
            for (int i = 0; i < 8; i++) a[i] = As[(tm * 8 + i) * 16 + kk];
            b0 = Bs[kk * 32 + tn * 2];
            b1 = Bs[kk * 32 + tn * 2 + 1];
            #pragma unroll
            for (int i = 0; i < 8; i++) {
                acc[i][0] += a[i] * b0;
                acc[i][1] += a[i] * b1;
            }
        }
        __syncthreads();
    }

    #pragma unroll
    for (int i = 0; i < 8; i++) {
        int m  = m0 + tm * 8 + i;
        int b_ = m >> 10, s = m & 1023;
        int bhs = (b_ * HH + h) * SS + s;
        #pragma unroll
        for (int j = 0; j < 2; j++) {
            int gn = n0 + tn * 2 + j;
            float v = acc[i][j];
            if (gn < DKK)           g_q[bhs * DKK + gn]            = v + bq[h * DKK + gn];
            else if (gn < 2 * DKK)  g_k[bhs * DKK + (gn - DKK)]    = v + bk[h * DKK + (gn - DKK)];
            else                    g_v[bhs * DVV + (gn - 2*DKK)]  = v + bv[h * DVV + (gn - 2*DKK)];
        }
    }
}

// ---------------------------------------------------------------------------
// Kernel 2: attention. One block = (b,h) x 16-query tile.
//  - scores tile [16][1024] kept in smem
//  - softmax in-block, weights streamed to gmem (write-only)
//  - PV accumulated in registers -> g_concat
// grid (64, 64), block 256, dynamic smem 86272 B
// ---------------------------------------------------------------------------
__global__ void attn_kernel(float* __restrict__ wout)
{
    extern __shared__ float sm[];
    float* qs = sm;                    // 16*64
    float* sc = sm + 16 * 64;          // 16*1024
    float* kv = sm + 16 * 64 + 16 * 1024; // 64*65 (k chunks, padded) / 64*33 (v)

    const int bh  = blockIdx.x;
    const int qt  = blockIdx.y;
    const int tid = threadIdx.x;
    const int base = bh * SS;
    const float inv_scale = 0.125f;   // 1/sqrt(64)

    // load 16x64 q tile
    #pragma unroll
    for (int i = 0; i < 4; i++) {
        int t = tid + i * 256;
        qs[t] = g_q[(base + qt * 16 + (t >> 6)) * DKK + (t & 63)];
    }
    __syncthreads();

    // --- scores: 16 chunks of 64 keys ---
    const int j  = tid & 63;
    const int rg = tid >> 6;   // 4 row groups of 4 rows
    for (int kc = 0; kc < 16; kc++) {
        #pragma unroll
        for (int i = 0; i < 16; i++) {
            int t = tid + i * 256;
            kv[(t >> 6) * 65 + (t & 63)] =
                g_k[(base + kc * 64 + (t >> 6)) * DKK + (t & 63)];
        }
        __syncthreads();
        float acc[4] = {0.f, 0.f, 0.f, 0.f};
        #pragma unroll 16
        for (int d = 0; d < 64; d++) {
            float kval = kv[j * 65 + d];
            #pragma unroll
            for (int i = 0; i < 4; i++)
                acc[i] += qs[(rg * 4 + i) * 64 + d] * kval;
        }
        #pragma unroll
        for (int i = 0; i < 4; i++)
            sc[(rg * 4 + i) * 1024 + kc * 64 + j] = acc[i] * inv_scale;
        __syncthreads();
    }

    // --- softmax per row (2 rows per warp) + stream weights ---
    const int warp = tid >> 5, lane = tid & 31;
    for (int rr = 0; rr < 2; rr++) {
        int row = warp * 2 + rr;
        float* srow = sc + row * 1024;
        float mx = -1e30f;
        for (int t = lane; t < 1024; t += 32) mx = fmaxf(mx, srow[t]);
        #pragma unroll
        for (int o = 16; o; o >>= 1) mx = fmaxf(mx, __shfl_xor_sync(0xffffffffu, mx, o));
        float sum = 0.f;
        for (int t = lane; t < 1024; t += 32) {
            float e = __expf(srow[t] - mx);
            srow[t] = e;
            sum += e;
        }
        #pragma unroll
        for (int o = 16; o; o >>= 1) sum += __shfl_xor_sync(0xffffffffu, sum, o);
        float inv = 1.f / sum;
        float* wrow = wout + ((long long)(bh * SS + qt * 16 + row)) * SS;
        for (int t = lane; t < 1024; t += 32) {
            float p = srow[t] * inv;
            srow[t] = p;
            wrow[t] = p;
        }
    }
    __syncthreads();

    // --- PV: out[16][32] ---
    const int col = tid & 31;
    const int rg2 = tid >> 5;  // 0..7 -> rows rg2 and rg2+8
    float o0 = 0.f, o1 = 0.f;
    for (int vc = 0; vc < 16; vc++) {
        #pragma unroll
        for (int i = 0; i < 8; i++) {
            int t = tid + i * 256;
            kv[(t >> 5) * 33 + (t & 31)] =
                g_v[(base + vc * 64 + (t >> 5)) * DVV + (t & 31)];
        }
        __syncthreads();
        #pragma unroll 8
        for (int jj = 0; jj < 64; jj++) {
            float vv = kv[jj * 33 + col];
            o0 += sc[rg2 * 1024 + vc * 64 + jj] * vv;
            o1 += sc[(rg2 + 8) * 1024 + vc * 64 + jj] * vv;
        }
        __syncthreads();
    }
    const int b_ = bh >> 4, h = bh & 15;
    const int s0 = qt * 16;
    g_concat[(b_ * SS + s0 + rg2)     * CDIM + h * DVV + col] = o0;
    g_concat[(b_ * SS + s0 + rg2 + 8) * CDIM + h * DVV + col] = o1;
}

// ---------------------------------------------------------------------------
// Kernel 3: output projection. [4096x512] @ Wo[512x1024] + bo
//  BM=64, BN=64, BK=16, 256 threads, 4x4 microtile.
// grid (64, 16)
// ---------------------------------------------------------------------------
__global__ void outproj_kernel(const float* __restrict__ Wo,
                               const float* __restrict__ bo,
                               float* __restrict__ out)
{
    __shared__ float As[64*16];
    __shared__ float Bs[16*64];
    const int tid = threadIdx.x;
    const int tn = tid & 15, tm = tid >> 4;
    const int m0 = blockIdx.x * 64, n0 = blockIdx.y * 64;

    float acc[4][4];
    #pragma unroll
    for (int i = 0; i < 4; i++)
        #pragma unroll
        for (int jj = 0; jj < 4; jj++) acc[i][jj] = 0.f;

    for (int k0 = 0; k0 < CDIM; k0 += 16) {
        #pragma unroll
        for (int i = 0; i < 4; i++) {
            int t = tid + i * 256;
            As[t] = g_concat[(m0 + (t >> 4)) * CDIM + k0 + (t & 15)];
        }
        #pragma unroll
        for (int i = 0; i < 4; i++) {
            int t = tid + i * 256;
            Bs[t] = Wo[(k0 + (t >> 6)) * DD + n0 + (t & 63)];
        }
        __syncthreads();
        #pragma unroll
        for (int kk = 0; kk < 16; kk++) {
            float a[4], b[4];
            #pragma unroll
            for (int i = 0; i < 4; i++) a[i] = As[(tm * 4 + i) * 16 + kk];
            #pragma unroll
            for (int jj = 0; jj < 4; jj++) b[jj] = Bs[kk * 64 + tn * 4 + jj];
            #pragma unroll
            for (int i = 0; i < 4; i++)
                #pragma unroll
                for (int jj = 0; jj < 4; jj++) acc[i][jj] += a[i] * b[jj];
        }
        __syncthreads();
    }

    #pragma unroll
    for (int i = 0; i < 4; i++) {
        int m = m0 + tm * 4 + i;
        #pragma unroll
        for (int jj = 0; jj < 4; jj++) {
            int n = n0 + tn * 4 + jj;
            out[m * DD + n] = acc[i][jj] + bo[n];
        }
    }
}

// ---------------------------------------------------------------------------
extern "C" void kernel_launch(void* const* d_in, const int* in_sizes, int n_in,
                              void* d_out, int out_size)
{
    const float* x  = (const float*)d_in[0];
    const float* Wq = (const float*)d_in[1];
    const float* bq = (const float*)d_in[2];
    const float* Wk = (const float*)d_in[3];
    const float* bk = (const float*)d_in[4];
    const float* Wv = (const float*)d_in[5];
    const float* bv = (const float*)d_in[6];
    const float* Wo = (const float*)d_in[7];
    const float* bo = (const float*)d_in[8];

    float* out  = (float*)d_out;
    // return order (output, weights): output [B,S,D] then weights [B,H,S,S]
    float* wptr = out + (size_t)BB * SS * DD;

    static bool attr_set = false;
    // idempotent, safe to call every launch (kept unconditional for determinism)
    cudaFuncSetAttribute(attn_kernel, cudaFuncAttributeMaxDynamicSharedMemorySize,
                         (16*64 + 16*1024 + 64*65) * (int)sizeof(float));
    (void)attr_set;

    proj_kernel<<<dim3(32, 5, 16), 256>>>(x, Wq, bq, Wk, bk, Wv, bv);
    attn_kernel<<<dim3(BH, SS/16), 256,
                  (16*64 + 16*1024 + 64*65) * sizeof(float)>>>(wptr);
    outproj_kernel<<<dim3(64, 16), 256>>>(Wo, bo, out);
}

// round 2
// speedup vs baseline: 1.6482x; 1.6482x over previous
#include <cuda_runtime.h>
#include <cuda_bf16.h>
#include <cstdint>

#define BB 4
#define SS 1024
#define DD 1024
#define HH 16
#define DKK 64
#define DVV 32
#define BH (BB*HH)          // 64
#define MM (BB*SS)          // 4096
#define CDIM (HH*DVV)       // 512
#define NQKV (HH*160)       // 2560

// Scratch (device globals — no allocation in kernel_launch)
__device__ float g_q[BH*SS*DKK];      // [B,H,S,DK]
__device__ float g_k[BH*SS*DKK];
__device__ float g_v[BH*SS*DVV];
__device__ float g_concat[MM*CDIM];   // [B,S,H*DV]

// ---------------------------------------------------------------------------
// helpers
// ---------------------------------------------------------------------------
__device__ __forceinline__ uint32_t smem_u32(const void* p){
    return (uint32_t)__cvta_generic_to_shared(p);
}
__device__ __forceinline__ void cp16(uint32_t dst, const void* src){
    asm volatile("cp.async.cg.shared.global [%0], [%1], 16;\n" :: "r"(dst), "l"(src));
}
__device__ __forceinline__ void cp_commit(){ asm volatile("cp.async.commit_group;\n"); }
template<int N> __device__ __forceinline__ void cp_wait(){
    asm volatile("cp.async.wait_group %0;\n" :: "n"(N));
}
__device__ __forceinline__ void mma_tf32(float* d, const uint32_t* a, const uint32_t* b){
    asm volatile(
      "mma.sync.aligned.m16n8k8.row.col.f32.tf32.tf32.f32 "
      "{%0,%1,%2,%3},{%4,%5,%6,%7},{%8,%9},{%0,%1,%2,%3};\n"
      : "+f"(d[0]),"+f"(d[1]),"+f"(d[2]),"+f"(d[3])
      : "r"(a[0]),"r"(a[1]),"r"(a[2]),"r"(a[3]),"r"(b[0]),"r"(b[1]));
}

// ---------------------------------------------------------------------------
// Kernel 1: fused QKV projection via tf32 mma.sync.
//  C[4096, 2560] = X[4096,1024] @ Wall[1024,2560]; column gn -> head gn/160,
//  offset gn%160: [0,64) Q, [64,128) K, [128,160) V.
//  BM=128, BN=128, BK=32, 256 threads (8 warps, warp tile 32x64).
//  2-stage cp.async pipeline. Conflict-free smem strides (A:36, B:136).
// grid (32, 20), dyn smem 71680 B
// ---------------------------------------------------------------------------
#define AS_STRIDE 36
#define BS_STRIDE 136
#define P_ASZ (128*AS_STRIDE)
#define P_BSZ (32*BS_STRIDE)
#define P_STAGE (P_ASZ + P_BSZ)

__global__ void __launch_bounds__(256,1) proj_mma(
    const float* __restrict__ x,
    const float* __restrict__ Wq, const float* __restrict__ bq,
    const float* __restrict__ Wk, const float* __restrict__ bk,
    const float* __restrict__ Wv, const float* __restrict__ bv)
{
    extern __shared__ float sm[];
    const int tid  = threadIdx.x;
    const int lane = tid & 31, warp = tid >> 5;
    const int wm = warp & 3, wn = warp >> 2;
    const int r = lane & 3, g = lane >> 2;
    const int m0 = blockIdx.x * 128;
    const int n0 = blockIdx.y * 128;

    uint32_t sbase = smem_u32(sm);

    float acc[2][8][4];
    #pragma unroll
    for (int mt = 0; mt < 2; mt++)
        #pragma unroll
        for (int nt = 0; nt < 8; nt++)
            #pragma unroll
            for (int i = 0; i < 4; i++) acc[mt][nt][i] = 0.f;

    // --- async tile load for stage s, k-offset k0 ---
    auto issue_load = [&](int s, int k0) {
        uint32_t abase = sbase + (uint32_t)(s * P_STAGE) * 4u;
        uint32_t bbase = abase + (uint32_t)P_ASZ * 4u;
        #pragma unroll
        for (int i = 0; i < 4; i++) {
            int flat = tid + i * 256;          // 1024 float4 chunks
            int row = flat >> 3, kc = (flat & 7) * 4;
            cp16(abase + (uint32_t)(row * AS_STRIDE + kc) * 4u,
                 &x[(size_t)(m0 + row) * DD + k0 + kc]);
        }
        #pragma unroll
        for (int i = 0; i < 4; i++) {
            int flat = tid + i * 256;
            int k = flat >> 5, nl = (flat & 31) * 4;
            int gn = n0 + nl;
            int h = gn / 160, off = gn - h * 160;
            const float* src;
            int dd = k0 + k;
            if (off < 64)        src = &Wq[((size_t)h * DD + dd) * DKK + off];
            else if (off < 128)  src = &Wk[((size_t)h * DD + dd) * DKK + (off - 64)];
            else                 src = &Wv[((size_t)h * DD + dd) * DVV + (off - 128)];
            cp16(bbase + (uint32_t)(k * BS_STRIDE + nl) * 4u, src);
        }
    };

    issue_load(0, 0);
    cp_commit();

    for (int it = 0; it < 32; it++) {
        if (it + 1 < 32) { issue_load((it + 1) & 1, (it + 1) * 32); cp_commit(); cp_wait<1>(); }
        else             { cp_wait<0>(); }
        __syncthreads();

        const float* As = sm + (it & 1) * P_STAGE;
        const float* Bs = As + P_ASZ;
        #pragma unroll
        for (int kt = 0; kt < 4; kt++) {
            uint32_t a[2][4], b[8][2];
            #pragma unroll
            for (int mt = 0; mt < 2; mt++) {
                int row = wm * 32 + mt * 16;
                a[mt][0] = __float_as_uint(As[(row + g)     * AS_STRIDE + kt*8 + r]);
                a[mt][1] = __float_as_uint(As[(row + g + 8) * AS_STRIDE + kt*8 + r]);
                a[mt][2] = __float_as_uint(As[(row + g)     * AS_STRIDE + kt*8 + r + 4]);
                a[mt][3] = __float_as_uint(As[(row + g + 8) * AS_STRIDE + kt*8 + r + 4]);
            }
            #pragma unroll
            for (int nt = 0; nt < 8; nt++) {
                int col = wn * 64 + nt * 8 + g;
                b[nt][0] = __float_as_uint(Bs[(kt*8 + r)     * BS_STRIDE + col]);
                b[nt][1] = __float_as_uint(Bs[(kt*8 + r + 4) * BS_STRIDE + col]);
            }
            #pragma unroll
            for (int mt = 0; mt < 2; mt++)
                #pragma unroll
                for (int nt = 0; nt < 8; nt++)
                    mma_tf32(acc[mt][nt], a[mt], b[nt]);
        }
        __syncthreads();
    }

    // --- epilogue: scatter to g_q/g_k/g_v with bias ---
    #pragma unroll
    for (int mt = 0; mt < 2; mt++) {
        int row0 = m0 + wm * 32 + mt * 16 + g;       // c0/c1 row; c2/c3 row+8
        #pragma unroll
        for (int nt = 0; nt < 8; nt++) {
            int gn = n0 + wn * 64 + nt * 8 + 2 * r;
            int h = gn / 160, off = gn - h * 160;
            float bia0, bia1;
            float* dst0; float* dst1; int stride;
            // resolve tensor / bias for col pair (off, off+1) (same tensor: even bounds)
            int b0_ = row0 >> 10, s0_ = row0 & 1023;
            int b1_ = (row0 + 8) >> 10, s1_ = (row0 + 8) & 1023;
            size_t bhs0, bhs1;
            if (off < 64) {
                bia0 = bq[h*DKK + off]; bia1 = bq[h*DKK + off + 1];
                bhs0 = ((size_t)(b0_*HH + h))*SS + s0_;
                bhs1 = ((size_t)(b1_*HH + h))*SS + s1_;
                dst0 = g_q + bhs0*DKK + off; dst1 = g_q + bhs1*DKK + off; stride = 0;
            } else if (off < 128) {
                int o = off - 64;
                bia0 = bk[h*DKK + o]; bia1 = bk[h*DKK + o + 1];
                bhs0 = ((size_t)(b0_*HH + h))*SS + s0_;
                bhs1 = ((size_t)(b1_*HH + h))*SS + s1_;
                dst0 = g_k + bhs0*DKK + o; dst1 = g_k + bhs1*DKK + o; stride = 0;
            } else {
                int o = off - 128;
                bia0 = bv[h*DVV + o]; bia1 = bv[h*DVV + o + 1];
                bhs0 = ((size_t)(b0_*HH + h))*SS + s0_;
                bhs1 = ((size_t)(b1_*HH + h))*SS + s1_;
                dst0 = g_v + bhs0*DVV + o; dst1 = g_v + bhs1*DVV + o; stride = 0;
            }
            (void)stride;
            float2 v0 = make_float2(acc[mt][nt][0] + bia0, acc[mt][nt][1] + bia1);
            float2 v1 = make_float2(acc[mt][nt][2] + bia0, acc[mt][nt][3] + bia1);
            *(float2*)dst0 = v0;
            *(float2*)dst1 = v1;
        }
    }
}

// ---------------------------------------------------------------------------
// Kernel 2: attention (unchanged from R1). One block = (b,h) x 16-query tile.
// grid (64, 64), block 256, dynamic smem 86272 B
// ---------------------------------------------------------------------------
__global__ void attn_kernel(float* __restrict__ wout)
{
    extern __shared__ float smn[];
    float* qs = smn;                      // 16*64
    float* sc = smn + 16 * 64;            // 16*1024
    float* kv = smn + 16 * 64 + 16 * 1024; // 64*65 / 64*33

    const int bh  = blockIdx.x;
    const int qt  = blockIdx.y;
    const int tid = threadIdx.x;
    const int base = bh * SS;
    const float inv_scale = 0.125f;

    #pragma unroll
    for (int i = 0; i < 4; i++) {
        int t = tid + i * 256;
        qs[t] = g_q[(base + qt * 16 + (t >> 6)) * DKK + (t & 63)];
    }
    __syncthreads();

    const int j  = tid & 63;
    const int rg = tid >> 6;
    for (int kc = 0; kc < 16; kc++) {
        #pragma unroll
        for (int i = 0; i < 16; i++) {
            int t = tid + i * 256;
            kv[(t >> 6) * 65 + (t & 63)] =
                g_k[(base + kc * 64 + (t >> 6)) * DKK + (t & 63)];
        }
        __syncthreads();
        float acc[4] = {0.f, 0.f, 0.f, 0.f};
        #pragma unroll 16
        for (int d = 0; d < 64; d++) {
            float kval = kv[j * 65 + d];
            #pragma unroll
            for (int i = 0; i < 4; i++)
                acc[i] += qs[(rg * 4 + i) * 64 + d] * kval;
        }
        #pragma unroll
        for (int i = 0; i < 4; i++)
            sc[(rg * 4 + i) * 1024 + kc * 64 + j] = acc[i] * inv_scale;
        __syncthreads();
    }

    const int warp = tid >> 5, lane = tid & 31;
    for (int rr = 0; rr < 2; rr++) {
        int row = warp * 2 + rr;
        float* srow = sc + row * 1024;
        float mx = -1e30f;
        for (int t = lane; t < 1024; t += 32) mx = fmaxf(mx, srow[t]);
        #pragma unroll
        for (int o = 16; o; o >>= 1) mx = fmaxf(mx, __shfl_xor_sync(0xffffffffu, mx, o));
        float sum = 0.f;
        for (int t = lane; t < 1024; t += 32) {
            float e = __expf(srow[t] - mx);
            srow[t] = e;
            sum += e;
        }
        #pragma unroll
        for (int o = 16; o; o >>= 1) sum += __shfl_xor_sync(0xffffffffu, sum, o);
        float inv = 1.f / sum;
        float* wrow = wout + ((long long)(bh * SS + qt * 16 + row)) * SS;
        for (int t = lane; t < 1024; t += 32) {
            float p = srow[t] * inv;
            srow[t] = p;
            wrow[t] = p;
        }
    }
    __syncthreads();

    const int col = tid & 31;
    const int rg2 = tid >> 5;
    float o0 = 0.f, o1 = 0.f;
    for (int vc = 0; vc < 16; vc++) {
        #pragma unroll
        for (int i = 0; i < 8; i++) {
            int t = tid + i * 256;
            kv[(t >> 5) * 33 + (t & 31)] =
                g_v[(base + vc * 64 + (t >> 5)) * DVV + (t & 31)];
        }
        __syncthreads();
        #pragma unroll 8
        for (int jj = 0; jj < 64; jj++) {
            float vv = kv[jj * 33 + col];
            o0 += sc[rg2 * 1024 + vc * 64 + jj] * vv;
            o1 += sc[(rg2 + 8) * 1024 + vc * 64 + jj] * vv;
        }
        __syncthreads();
    }
    const int b_ = bh >> 4, h = bh & 15;
    const int s0 = qt * 16;
    g_concat[(b_ * SS + s0 + rg2)     * CDIM + h * DVV + col] = o0;
    g_concat[(b_ * SS + s0 + rg2 + 8) * CDIM + h * DVV + col] = o1;
}

// ---------------------------------------------------------------------------
// Kernel 3: output projection via tf32 mma.sync.
//  out[4096,1024] = g_concat[4096,512] @ Wo[512,1024] + bo
//  Same tiling as proj_mma; K=512 -> 16 iters. grid (32, 8)
// ---------------------------------------------------------------------------
__global__ void __launch_bounds__(256,1) outproj_mma(
    const float* __restrict__ Wo, const float* __restrict__ bo,
    float* __restrict__ out)
{
    extern __shared__ float sm[];
    const int tid  = threadIdx.x;
    const int lane = tid & 31, warp = tid >> 5;
    const int wm = warp & 3, wn = warp >> 2;
    const int r = lane & 3, g = lane >> 2;
    const int m0 = blockIdx.x * 128;
    const int n0 = blockIdx.y * 128;

    uint32_t sbase = smem_u32(sm);

    float acc[2][8][4];
    #pragma unroll
    for (int mt = 0; mt < 2; mt++)
        #pragma unroll
        for (int nt = 0; nt < 8; nt++)
            #pragma unroll
            for (int i = 0; i < 4; i++) acc[mt][nt][i] = 0.f;

    auto issue_load = [&](int s, int k0) {
        uint32_t abase = sbase + (uint32_t)(s * P_STAGE) * 4u;
        uint32_t bbase = abase + (uint32_t)P_ASZ * 4u;
        #pragma unroll
        for (int i = 0; i < 4; i++) {
            int flat = tid + i * 256;
            int row = flat >> 3, kc = (flat & 7) * 4;
            cp16(abase + (uint32_t)(row * AS_STRIDE + kc) * 4u,
                 &g_concat[(size_t)(m0 + row) * CDIM + k0 + kc]);
        }
        #pragma unroll
        for (int i = 0; i < 4; i++) {
            int flat = tid + i * 256;
            int k = flat >> 5, nl = (flat & 31) * 4;
            cp16(bbase + (uint32_t)(k * BS_STRIDE + nl) * 4u,
                 &Wo[(size_t)(k0 + k) * DD + n0 + nl]);
        }
    };

    issue_load(0, 0);
    cp_commit();

    for (int it = 0; it < 16; it++) {
        if (it + 1 < 16) { issue_load((it + 1) & 1, (it + 1) * 32); cp_commit(); cp_wait<1>(); }
        else             { cp_wait<0>(); }
        __syncthreads();

        const float* As = sm + (it & 1) * P_STAGE;
        const float* Bs = As + P_ASZ;
        #pragma unroll
        for (int kt = 0; kt < 4; kt++) {
            uint32_t a[2][4], b[8][2];
            #pragma unroll
            for (int mt = 0; mt < 2; mt++) {
                int row = wm * 32 + mt * 16;
                a[mt][0] = __float_as_uint(As[(row + g)     * AS_STRIDE + kt*8 + r]);
                a[mt][1] = __float_as_uint(As[(row + g + 8) * AS_STRIDE + kt*8 + r]);
                a[mt][2] = __float_as_uint(As[(row + g)     * AS_STRIDE + kt*8 + r + 4]);
                a[mt][3] = __float_as_uint(As[(row + g + 8) * AS_STRIDE + kt*8 + r + 4]);
            }
            #pragma unroll
            for (int nt = 0; nt < 8; nt++) {
                int col = wn * 64 + nt * 8 + g;
                b[nt][0] = __float_as_uint(Bs[(kt*8 + r)     * BS_STRIDE + col]);
                b[nt][1] = __float_as_uint(Bs[(kt*8 + r + 4) * BS_STRIDE + col]);
            }
            #pragma unroll
            for (int mt = 0; mt < 2; mt++)
                #pragma unroll
                for (int nt = 0; nt < 8; nt++)
                    mma_tf32(acc[mt][nt], a[mt], b[nt]);
        }
        __syncthreads();
    }

    #pragma unroll
    for (int mt = 0; mt < 2; mt++) {
        int row0 = m0 + wm * 32 + mt * 16 + g;
        #pragma unroll
        for (int nt = 0; nt < 8; nt++) {
            int gn = n0 + wn * 64 + nt * 8 + 2 * r;
            float bia0 = bo[gn], bia1 = bo[gn + 1];
            float2 v0 = make_float2(acc[mt][nt][0] + bia0, acc[mt][nt][1] + bia1);
            float2 v1 = make_float2(acc[mt][nt][2] + bia0, acc[mt][nt][3] + bia1);
            *(float2*)&out[(size_t)row0 * DD + gn] = v0;
            *(float2*)&out[(size_t)(row0 + 8) * DD + gn] = v1;
        }
    }
}

// ---------------------------------------------------------------------------
extern "C" void kernel_launch(void* const* d_in, const int* in_sizes, int n_in,
                              void* d_out, int out_size)
{
    const float* x  = (const float*)d_in[0];
    const float* Wq = (const float*)d_in[1];
    const float* bq = (const float*)d_in[2];
    const float* Wk = (const float*)d_in[3];
    const float* bk = (const float*)d_in[4];
    const float* Wv = (const float*)d_in[5];
    const float* bv = (const float*)d_in[6];
    const float* Wo = (const float*)d_in[7];
    const float* bo = (const float*)d_in[8];

    float* out  = (float*)d_out;
    float* wptr = out + (size_t)BB * SS * DD;   // weights after output

    const int proj_smem = 2 * P_STAGE * (int)sizeof(float);   // 71680
    const int attn_smem = (16*64 + 16*1024 + 64*65) * (int)sizeof(float);

    cudaFuncSetAttribute(proj_mma, cudaFuncAttributeMaxDynamicSharedMemorySize, proj_smem);
    cudaFuncSetAttribute(outproj_mma, cudaFuncAttributeMaxDynamicSharedMemorySize, proj_smem);
    cudaFuncSetAttribute(attn_kernel, cudaFuncAttributeMaxDynamicSharedMemorySize, attn_smem);

    proj_mma<<<dim3(MM/128, NQKV/128), 256, proj_smem>>>(x, Wq, bq, Wk, bk, Wv, bv);
    attn_kernel<<<dim3(BH, SS/16), 256, attn_smem>>>(wptr);
    outproj_mma<<<dim3(MM/128, DD/128), 256, proj_smem>>>(Wo, bo, out);
}

// round 3
// speedup vs baseline: 2.4585x; 1.4917x over previous
#include <cuda_runtime.h>
#include <cuda_bf16.h>
#include <cstdint>

#define BB 4
#define SS 1024
#define DD 1024
#define HH 16
#define DKK 64
#define DVV 32
#define BH (BB*HH)          // 64
#define MM (BB*SS)          // 4096
#define CDIM (HH*DVV)       // 512
#define NQKV (HH*160)       // 2560

// Scratch (device globals — no allocation in kernel_launch)
__device__ float g_q[BH*SS*DKK];      // [B,H,S,DK]
__device__ float g_k[BH*SS*DKK];
__device__ float g_v[BH*SS*DVV];
__device__ float g_concat[MM*CDIM];   // [B,S,H*DV]

// ---------------------------------------------------------------------------
// helpers
// ---------------------------------------------------------------------------
__device__ __forceinline__ uint32_t smem_u32(const void* p){
    return (uint32_t)__cvta_generic_to_shared(p);
}
__device__ __forceinline__ void cp16(uint32_t dst, const void* src){
    asm volatile("cp.async.cg.shared.global [%0], [%1], 16;\n" :: "r"(dst), "l"(src));
}
__device__ __forceinline__ void cp_commit(){ asm volatile("cp.async.commit_group;\n"); }
template<int N> __device__ __forceinline__ void cp_wait(){
    asm volatile("cp.async.wait_group %0;\n" :: "n"(N));
}
__device__ __forceinline__ void mma_tf32(float* d, const uint32_t* a, const uint32_t* b){
    asm volatile(
      "mma.sync.aligned.m16n8k8.row.col.f32.tf32.tf32.f32 "
      "{%0,%1,%2,%3},{%4,%5,%6,%7},{%8,%9},{%0,%1,%2,%3};\n"
      : "+f"(d[0]),"+f"(d[1]),"+f"(d[2]),"+f"(d[3])
      : "r"(a[0]),"r"(a[1]),"r"(a[2]),"r"(a[3]),"r"(b[0]),"r"(b[1]));
}
// hi part = fp32 with low 13 mantissa bits cleared (== HW tf32 truncation)
__device__ __forceinline__ void split_tf32(float f, uint32_t& hi, uint32_t& lo){
    hi = __float_as_uint(f) & 0xFFFFE000u;
    lo = __float_as_uint(f - __uint_as_float(hi));
}

// ---------------------------------------------------------------------------
// Kernel 1: fused QKV projection, SPLIT tf32 (3 MMAs: hh + hl + lh).
//  C[4096,2560] = X[4096,1024] @ Wall, cols: head gn/160, off gn%160
//  BM=128, BN=128, BK=32, 8 warps, warp tile 64x32 (mt=4, nt=4).
// grid (32, 20), dyn smem 71680 B
// ---------------------------------------------------------------------------
#define AS_STRIDE 36
#define BS_STRIDE 136
#define P_ASZ (128*AS_STRIDE)
#define P_BSZ (32*BS_STRIDE)
#define P_STAGE (P_ASZ + P_BSZ)

__global__ void __launch_bounds__(256,1) proj_mma(
    const float* __restrict__ x,
    const float* __restrict__ Wq, const float* __restrict__ bq,
    const float* __restrict__ Wk, const float* __restrict__ bk,
    const float* __restrict__ Wv, const float* __restrict__ bv)
{
    extern __shared__ float sm[];
    const int tid  = threadIdx.x;
    const int lane = tid & 31, warp = tid >> 5;
    const int wm = warp & 1, wn = warp >> 1;     // 2 x 4 warp grid
    const int r = lane & 3, g = lane >> 2;
    const int m0 = blockIdx.x * 128;
    const int n0 = blockIdx.y * 128;

    uint32_t sbase = smem_u32(sm);

    float acc[4][4][4];
    #pragma unroll
    for (int mt = 0; mt < 4; mt++)
        #pragma unroll
        for (int nt = 0; nt < 4; nt++)
            #pragma unroll
            for (int i = 0; i < 4; i++) acc[mt][nt][i] = 0.f;

    auto issue_load = [&](int s, int k0) {
        uint32_t abase = sbase + (uint32_t)(s * P_STAGE) * 4u;
        uint32_t bbase = abase + (uint32_t)P_ASZ * 4u;
        #pragma unroll
        for (int i = 0; i < 4; i++) {
            int flat = tid + i * 256;
            int row = flat >> 3, kc = (flat & 7) * 4;
            cp16(abase + (uint32_t)(row * AS_STRIDE + kc) * 4u,
                 &x[(size_t)(m0 + row) * DD + k0 + kc]);
        }
        #pragma unroll
        for (int i = 0; i < 4; i++) {
            int flat = tid + i * 256;
            int k = flat >> 5, nl = (flat & 31) * 4;
            int gn = n0 + nl;
            int h = gn / 160, off = gn - h * 160;
            const float* src;
            int dd = k0 + k;
            if (off < 64)        src = &Wq[((size_t)h * DD + dd) * DKK + off];
            else if (off < 128)  src = &Wk[((size_t)h * DD + dd) * DKK + (off - 64)];
            else                 src = &Wv[((size_t)h * DD + dd) * DVV + (off - 128)];
            cp16(bbase + (uint32_t)(k * BS_STRIDE + nl) * 4u, src);
        }
    };

    issue_load(0, 0);
    cp_commit();

    for (int it = 0; it < 32; it++) {
        if (it + 1 < 32) { issue_load((it + 1) & 1, (it + 1) * 32); cp_commit(); cp_wait<1>(); }
        else             { cp_wait<0>(); }
        __syncthreads();

        const float* As = sm + (it & 1) * P_STAGE;
        const float* Bs = As + P_ASZ;
        #pragma unroll
        for (int kt = 0; kt < 4; kt++) {
            uint32_t ah[4][4], al[4][4], bhf[4][2], blf[4][2];
            #pragma unroll
            for (int mt = 0; mt < 4; mt++) {
                int row = wm * 64 + mt * 16;
                float f0 = As[(row + g)     * AS_STRIDE + kt*8 + r];
                float f1 = As[(row + g + 8) * AS_STRIDE + kt*8 + r];
                float f2 = As[(row + g)     * AS_STRIDE + kt*8 + r + 4];
                float f3 = As[(row + g + 8) * AS_STRIDE + kt*8 + r + 4];
                split_tf32(f0, ah[mt][0], al[mt][0]);
                split_tf32(f1, ah[mt][1], al[mt][1]);
                split_tf32(f2, ah[mt][2], al[mt][2]);
                split_tf32(f3, ah[mt][3], al[mt][3]);
            }
            #pragma unroll
            for (int nt = 0; nt < 4; nt++) {
                int col = wn * 32 + nt * 8 + g;
                float f0 = Bs[(kt*8 + r)     * BS_STRIDE + col];
                float f1 = Bs[(kt*8 + r + 4) * BS_STRIDE + col];
                split_tf32(f0, bhf[nt][0], blf[nt][0]);
                split_tf32(f1, bhf[nt][1], blf[nt][1]);
            }
            #pragma unroll
            for (int mt = 0; mt < 4; mt++)
                #pragma unroll
                for (int nt = 0; nt < 4; nt++) {
                    mma_tf32(acc[mt][nt], ah[mt], bhf[nt]);
                    mma_tf32(acc[mt][nt], ah[mt], blf[nt]);
                    mma_tf32(acc[mt][nt], al[mt], bhf[nt]);
                }
        }
        __syncthreads();
    }

    // epilogue: scatter to g_q/g_k/g_v with bias
    #pragma unroll
    for (int mt = 0; mt < 4; mt++) {
        int row0 = m0 + wm * 64 + mt * 16 + g;
        #pragma unroll
        for (int nt = 0; nt < 4; nt++) {
            int gn = n0 + wn * 32 + nt * 8 + 2 * r;
            int h = gn / 160, off = gn - h * 160;
            float bia0, bia1;
            float *dst0, *dst1;
            int b0_ = row0 >> 10, s0_ = row0 & 1023;
            int b1_ = (row0 + 8) >> 10, s1_ = (row0 + 8) & 1023;
            size_t bhs0, bhs1;
            if (off < 64) {
                bia0 = bq[h*DKK + off]; bia1 = bq[h*DKK + off + 1];
                bhs0 = ((size_t)(b0_*HH + h))*SS + s0_;
                bhs1 = ((size_t)(b1_*HH + h))*SS + s1_;
                dst0 = g_q + bhs0*DKK + off; dst1 = g_q + bhs1*DKK + off;
            } else if (off < 128) {
                int o = off - 64;
                bia0 = bk[h*DKK + o]; bia1 = bk[h*DKK + o + 1];
                bhs0 = ((size_t)(b0_*HH + h))*SS + s0_;
                bhs1 = ((size_t)(b1_*HH + h))*SS + s1_;
                dst0 = g_k + bhs0*DKK + o; dst1 = g_k + bhs1*DKK + o;
            } else {
                int o = off - 128;
                bia0 = bv[h*DVV + o]; bia1 = bv[h*DVV + o + 1];
                bhs0 = ((size_t)(b0_*HH + h))*SS + s0_;
                bhs1 = ((size_t)(b1_*HH + h))*SS + s1_;
                dst0 = g_v + bhs0*DVV + o; dst1 = g_v + bhs1*DVV + o;
            }
            *(float2*)dst0 = make_float2(acc[mt][nt][0] + bia0, acc[mt][nt][1] + bia1);
            *(float2*)dst1 = make_float2(acc[mt][nt][2] + bia0, acc[mt][nt][3] + bia1);
        }
    }
}

// ---------------------------------------------------------------------------
// Kernel 2: attention via tf32 mma. Block = (bh, 32-query tile), 256 thr.
//  - scores kept as exp(s) fp32 in smem [32][1028] (no max subtraction:
//    s = q.k/8 is O(1), exp is fp32-safe; softmax identical in exact math)
//  - QK^T + PV on tensor pipe; K/V double-buffered cp.async
//  - weights streamed normalized; PV normalized at epilogue
// grid (64, 32), dyn smem 195712 B
// ---------------------------------------------------------------------------
#define QROWS 32
#define QS_STR 68
#define SC_STR 1028
#define KS_STR 68
#define VS_STR 40

__global__ void __launch_bounds__(256,1) attn_mma(float* __restrict__ wout)
{
    extern __shared__ float sm[];
    float* qs   = sm;                          // 32*68
    float* sc   = qs + QROWS*QS_STR;           // 32*1028
    float* ks   = sc + QROWS*SC_STR;           // 2*64*68
    float* vs   = ks + 2*64*KS_STR;            // 2*64*40
    float* sinv = vs + 2*64*VS_STR;            // 32

    const int bh = blockIdx.x, qt = blockIdx.y;
    const int tid = threadIdx.x;
    const int lane = tid & 31, warp = tid >> 5;
    const int r = lane & 3, g = lane >> 2;
    const size_t base = (size_t)bh * SS;

    uint32_t qsa = smem_u32(qs), ksa = smem_u32(ks), vsa = smem_u32(vs);

    // prologue: Q tile + K chunk 0, one group
    #pragma unroll
    for (int i = 0; i < 2; i++) {
        int flat = tid + i * 256;                 // 512 f4
        int row = flat >> 4, c4 = (flat & 15) * 4;
        cp16(qsa + (uint32_t)(row * QS_STR + c4) * 4u,
             &g_q[(base + qt * QROWS + row) * DKK + c4]);
    }
    #pragma unroll
    for (int i = 0; i < 4; i++) {
        int flat = tid + i * 256;                 // 1024 f4
        int key = flat >> 4, c4 = (flat & 15) * 4;
        cp16(ksa + (uint32_t)(key * KS_STR + c4) * 4u,
             &g_k[(base + key) * DKK + c4]);
    }
    cp_commit();

    uint32_t qa[2][8][4];  // hoisted Q fragments (2 m16 x 8 k-steps)

    // ---- scores: 16 chunks of 64 keys ----
    for (int kc = 0; kc < 16; kc++) {
        if (kc + 1 < 16) {
            uint32_t dstb = ksa + (uint32_t)(((kc + 1) & 1) * 64 * KS_STR) * 4u;
            #pragma unroll
            for (int i = 0; i < 4; i++) {
                int flat = tid + i * 256;
                int key = flat >> 4, c4 = (flat & 15) * 4;
                cp16(dstb + (uint32_t)(key * KS_STR + c4) * 4u,
                     &g_k[(base + (kc + 1) * 64 + key) * DKK + c4]);
            }
            cp_commit(); cp_wait<1>();
        } else cp_wait<0>();
        __syncthreads();

        if (kc == 0) {
            #pragma unroll
            for (int mt = 0; mt < 2; mt++)
                #pragma unroll
                for (int kt = 0; kt < 8; kt++) {
                    int row = mt * 16;
                    qa[mt][kt][0] = __float_as_uint(qs[(row + g)     * QS_STR + kt*8 + r]);
                    qa[mt][kt][1] = __float_as_uint(qs[(row + g + 8) * QS_STR + kt*8 + r]);
                    qa[mt][kt][2] = __float_as_uint(qs[(row + g)     * QS_STR + kt*8 + r + 4]);
                    qa[mt][kt][3] = __float_as_uint(qs[(row + g + 8) * QS_STR + kt*8 + r + 4]);
                }
        }

        const float* kb = ks + (kc & 1) * 64 * KS_STR;
        float accs[2][4] = {{0.f,0.f,0.f,0.f},{0.f,0.f,0.f,0.f}};
        #pragma unroll
        for (int kt = 0; kt < 8; kt++) {
            uint32_t bb[2];
            bb[0] = __float_as_uint(kb[(warp*8 + g) * KS_STR + kt*8 + r]);
            bb[1] = __float_as_uint(kb[(warp*8 + g) * KS_STR + kt*8 + r + 4]);
            mma_tf32(accs[0], qa[0][kt], bb);
            mma_tf32(accs[1], qa[1][kt], bb);
        }
        int keyb = kc * 64 + warp * 8;
        #pragma unroll
        for (int mt = 0; mt < 2; mt++) {
            float e0 = __expf(accs[mt][0] * 0.125f);
            float e1 = __expf(accs[mt][1] * 0.125f);
            float e2 = __expf(accs[mt][2] * 0.125f);
            float e3 = __expf(accs[mt][3] * 0.125f);
            int row = mt * 16 + g;
            *(float2*)(sc + row * SC_STR + keyb + 2*r)       = make_float2(e0, e1);
            *(float2*)(sc + (row + 8) * SC_STR + keyb + 2*r) = make_float2(e2, e3);
        }
        __syncthreads();
    }

    // prefetch V chunk 0 (into untouched vs region — no race)
    #pragma unroll
    for (int i = 0; i < 2; i++) {
        int flat = tid + i * 256;                 // 512 f4
        int key = flat >> 3, c4 = (flat & 7) * 4;
        cp16(vsa + (uint32_t)(key * VS_STR + c4) * 4u,
             &g_v[(base + key) * DVV + c4]);
    }
    cp_commit();

    // ---- row sums -> 1/sum ----
    {
        int row0 = warp * 4;
        #pragma unroll
        for (int rr = 0; rr < 4; rr++) {
            int row = row0 + rr;
            float s = 0.f;
            #pragma unroll
            for (int i = 0; i < 8; i++) {
                float4 v = *(const float4*)(sc + row * SC_STR + lane * 4 + i * 128);
                s += v.x + v.y + v.z + v.w;
            }
            #pragma unroll
            for (int o = 16; o; o >>= 1) s += __shfl_xor_sync(0xffffffffu, s, o);
            if (lane == 0) sinv[row] = 1.f / s;
        }
    }
    __syncthreads();

    // ---- stream normalized weights ----
    #pragma unroll 4
    for (int i = 0; i < 32; i++) {
        int f = tid + i * 256;
        int row = f >> 8, c4 = (f & 255) * 4;
        float4 v = *(const float4*)(sc + row * SC_STR + c4);
        float iv = sinv[row];
        v.x *= iv; v.y *= iv; v.z *= iv; v.w *= iv;
        *(float4*)(wout + ((base + qt * QROWS + row) << 10) + c4) = v;
    }

    // ---- PV: out[32][32], warp -> one m16n8 tile ----
    const int mtp = warp & 1, ntp = warp >> 1;
    float pacc[4] = {0.f, 0.f, 0.f, 0.f};
    for (int vc = 0; vc < 16; vc++) {
        if (vc + 1 < 16) {
            uint32_t dstb = vsa + (uint32_t)(((vc + 1) & 1) * 64 * VS_STR) * 4u;
            #pragma unroll
            for (int i = 0; i < 2; i++) {
                int flat = tid + i * 256;
                int key = flat >> 3, c4 = (flat & 7) * 4;
                cp16(dstb + (uint32_t)(key * VS_STR + c4) * 4u,
                     &g_v[(base + (vc + 1) * 64 + key) * DVV + c4]);
            }
            cp_commit(); cp_wait<1>();
        } else cp_wait<0>();
        __syncthreads();

        const float* vb = vs + (vc & 1) * 64 * VS_STR;
        #pragma unroll
        for (int kt = 0; kt < 8; kt++) {
            uint32_t a[4], b[2];
            int row = mtp * 16;
            int col = vc * 64 + kt * 8;
            a[0] = __float_as_uint(sc[(row + g)     * SC_STR + col + r]);
            a[1] = __float_as_uint(sc[(row + g + 8) * SC_STR + col + r]);
            a[2] = __float_as_uint(sc[(row + g)     * SC_STR + col + r + 4]);
            a[3] = __float_as_uint(sc[(row + g + 8) * SC_STR + col + r + 4]);
            b[0] = __float_as_uint(vb[(kt*8 + r)     * VS_STR + ntp*8 + g]);
            b[1] = __float_as_uint(vb[(kt*8 + r + 4) * VS_STR + ntp*8 + g]);
            mma_tf32(pacc, a, b);
        }
        __syncthreads();
    }

    // epilogue: normalize + write g_concat
    {
        int row0 = mtp * 16 + g;
        float i0 = sinv[row0], i1 = sinv[row0 + 8];
        int b_ = bh >> 4, h = bh & 15;
        size_t o0 = ((size_t)(b_ * SS + qt * QROWS + row0)) * CDIM + h * DVV + ntp * 8 + 2 * r;
        *(float2*)(g_concat + o0)            = make_float2(pacc[0] * i0, pacc[1] * i0);
        *(float2*)(g_concat + o0 + 8 * CDIM) = make_float2(pacc[2] * i1, pacc[3] * i1);
    }
}

// ---------------------------------------------------------------------------
// Kernel 3: output projection, SPLIT tf32.
//  out[4096,1024] = g_concat[4096,512] @ Wo[512,1024] + bo
// grid (32, 8), dyn smem 71680 B
// ---------------------------------------------------------------------------
__global__ void __launch_bounds__(256,1) outproj_mma(
    const float* __restrict__ Wo, const float* __restrict__ bo,
    float* __restrict__ out)
{
    extern __shared__ float sm[];
    const int tid  = threadIdx.x;
    const int lane = tid & 31, warp = tid >> 5;
    const int wm = warp & 1, wn = warp >> 1;
    const int r = lane & 3, g = lane >> 2;
    const int m0 = blockIdx.x * 128;
    const int n0 = blockIdx.y * 128;

    uint32_t sbase = smem_u32(sm);

    float acc[4][4][4];
    #pragma unroll
    for (int mt = 0; mt < 4; mt++)
        #pragma unroll
        for (int nt = 0; nt < 4; nt++)
            #pragma unroll
            for (int i = 0; i < 4; i++) acc[mt][nt][i] = 0.f;

    auto issue_load = [&](int s, int k0) {
        uint32_t abase = sbase + (uint32_t)(s * P_STAGE) * 4u;
        uint32_t bbase = abase + (uint32_t)P_ASZ * 4u;
        #pragma unroll
        for (int i = 0; i < 4; i++) {
            int flat = tid + i * 256;
            int row = flat >> 3, kc = (flat & 7) * 4;
            cp16(abase + (uint32_t)(row * AS_STRIDE + kc) * 4u,
                 &g_concat[(size_t)(m0 + row) * CDIM + k0 + kc]);
        }
        #pragma unroll
        for (int i = 0; i < 4; i++) {
            int flat = tid + i * 256;
            int k = flat >> 5, nl = (flat & 31) * 4;
            cp16(bbase + (uint32_t)(k * BS_STRIDE + nl) * 4u,
                 &Wo[(size_t)(k0 + k) * DD + n0 + nl]);
        }
    };

    issue_load(0, 0);
    cp_commit();

    for (int it = 0; it < 16; it++) {
        if (it + 1 < 16) { issue_load((it + 1) & 1, (it + 1) * 32); cp_commit(); cp_wait<1>(); }
        else             { cp_wait<0>(); }
        __syncthreads();

        const float* As = sm + (it & 1) * P_STAGE;
        const float* Bs = As + P_ASZ;
        #pragma unroll
        for (int kt = 0; kt < 4; kt++) {
            uint32_t ah[4][4], al[4][4], bhf[4][2], blf[4][2];
            #pragma unroll
            for (int mt = 0; mt < 4; mt++) {
                int row = wm * 64 + mt * 16;
                float f0 = As[(row + g)     * AS_STRIDE + kt*8 + r];
                float f1 = As[(row + g + 8) * AS_STRIDE + kt*8 + r];
                float f2 = As[(row + g)     * AS_STRIDE + kt*8 + r + 4];
                float f3 = As[(row + g + 8) * AS_STRIDE + kt*8 + r + 4];
                split_tf32(f0, ah[mt][0], al[mt][0]);
                split_tf32(f1, ah[mt][1], al[mt][1]);
                split_tf32(f2, ah[mt][2], al[mt][2]);
                split_tf32(f3, ah[mt][3], al[mt][3]);
            }
            #pragma unroll
            for (int nt = 0; nt < 4; nt++) {
                int col = wn * 32 + nt * 8 + g;
                float f0 = Bs[(kt*8 + r)     * BS_STRIDE + col];
                float f1 = Bs[(kt*8 + r + 4) * BS_STRIDE + col];
                split_tf32(f0, bhf[nt][0], blf[nt][0]);
                split_tf32(f1, bhf[nt][1], blf[nt][1]);
            }
            #pragma unroll
            for (int mt = 0; mt < 4; mt++)
                #pragma unroll
                for (int nt = 0; nt < 4; nt++) {
                    mma_tf32(acc[mt][nt], ah[mt], bhf[nt]);
                    mma_tf32(acc[mt][nt], ah[mt], blf[nt]);
                    mma_tf32(acc[mt][nt], al[mt], bhf[nt]);
                }
        }
        __syncthreads();
    }

    #pragma unroll
    for (int mt = 0; mt < 4; mt++) {
        int row0 = m0 + wm * 64 + mt * 16 + g;
        #pragma unroll
        for (int nt = 0; nt < 4; nt++) {
            int gn = n0 + wn * 32 + nt * 8 + 2 * r;
            float bia0 = bo[gn], bia1 = bo[gn + 1];
            *(float2*)&out[(size_t)row0 * DD + gn] =
                make_float2(acc[mt][nt][0] + bia0, acc[mt][nt][1] + bia1);
            *(float2*)&out[(size_t)(row0 + 8) * DD + gn] =
                make_float2(acc[mt][nt][2] + bia0, acc[mt][nt][3] + bia1);
        }
    }
}

// ---------------------------------------------------------------------------
extern "C" void kernel_launch(void* const* d_in, const int* in_sizes, int n_in,
                              void* d_out, int out_size)
{
    const float* x  = (const float*)d_in[0];
    const float* Wq = (const float*)d_in[1];
    const float* bq = (const float*)d_in[2];
    const float* Wk = (const float*)d_in[3];
    const float* bk = (const float*)d_in[4];
    const float* Wv = (const float*)d_in[5];
    const float* bv = (const float*)d_in[6];
    const float* Wo = (const float*)d_in[7];
    const float* bo = (const float*)d_in[8];

    float* out  = (float*)d_out;
    float* wptr = out + (size_t)BB * SS * DD;   // weights after output

    const int proj_smem = 2 * P_STAGE * (int)sizeof(float);   // 71680
    const int attn_smem = (QROWS*QS_STR + QROWS*SC_STR + 2*64*KS_STR
                           + 2*64*VS_STR + 32) * (int)sizeof(float); // 195712

    cudaFuncSetAttribute(proj_mma,    cudaFuncAttributeMaxDynamicSharedMemorySize, proj_smem);
    cudaFuncSetAttribute(outproj_mma, cudaFuncAttributeMaxDynamicSharedMemorySize, proj_smem);
    cudaFuncSetAttribute(attn_mma,    cudaFuncAttributeMaxDynamicSharedMemorySize, attn_smem);

    proj_mma<<<dim3(MM/128, NQKV/128), 256, proj_smem>>>(x, Wq, bq, Wk, bk, Wv, bv);
    attn_mma<<<dim3(BH, SS/QROWS), 256, attn_smem>>>(wptr);
    outproj_mma<<<dim3(MM/128, DD/128), 256, proj_smem>>>(Wo, bo, out);
}

// round 4
// speedup vs baseline: 2.7565x; 1.1212x over previous
#include <cuda_runtime.h>
#include <cuda_bf16.h>
#include <cstdint>

#define BB 4
#define SS 1024
#define DD 1024
#define HH 16
#define DKK 64
#define DVV 32
#define BH (BB*HH)          // 64
#define MM (BB*SS)          // 4096
#define CDIM (HH*DVV)       // 512
#define NQKV (HH*160)       // 2560

// fp32 intermediates
__device__ float g_q[BH*SS*DKK];
__device__ float g_k[BH*SS*DKK];
__device__ float g_v[BH*SS*DVV];

// packed bf16x2 split operands (hi/lo)
__device__ uint32_t XH[MM*512],  XL[MM*512];       // x colpair-packed [4096][512]
__device__ uint32_t WH[512*NQKV], WL[512*NQKV];    // fused W kpair-packed [512][2560]
__device__ uint32_t WOH[256*DD],  WOL[256*DD];     // Wo kpair-packed [256][1024]
__device__ uint32_t QH[BH*SS*32], QL[BH*SS*32];    // q colpair-packed [bh*1024][32]
__device__ uint32_t KH[BH*SS*32], KL[BH*SS*32];    // k colpair-packed
__device__ uint32_t VH[BH*512*32], VL[BH*512*32];  // v keypair-packed [bh][512][32]
__device__ uint32_t GCH[MM*256],  GCL[MM*256];     // concat colpair-packed [4096][256]

// ---------------------------------------------------------------------------
// helpers
// ---------------------------------------------------------------------------
__device__ __forceinline__ uint32_t smem_u32(const void* p){
    return (uint32_t)__cvta_generic_to_shared(p);
}
__device__ __forceinline__ void cp16(uint32_t dst, const void* src){
    asm volatile("cp.async.cg.shared.global [%0], [%1], 16;\n" :: "r"(dst), "l"(src));
}
__device__ __forceinline__ void cp_commit(){ asm volatile("cp.async.commit_group;\n"); }
template<int N> __device__ __forceinline__ void cp_wait(){
    asm volatile("cp.async.wait_group %0;\n" :: "n"(N));
}
__device__ __forceinline__ void mma_bf16(float* d, const uint32_t* a, const uint32_t* b){
    asm volatile(
      "mma.sync.aligned.m16n8k16.row.col.f32.bf16.bf16.f32 "
      "{%0,%1,%2,%3},{%4,%5,%6,%7},{%8,%9},{%0,%1,%2,%3};\n"
      : "+f"(d[0]),"+f"(d[1]),"+f"(d[2]),"+f"(d[3])
      : "r"(a[0]),"r"(a[1]),"r"(a[2]),"r"(a[3]),"r"(b[0]),"r"(b[1]));
}
__device__ __forceinline__ uint32_t b2u(__nv_bfloat162 h){
    return *reinterpret_cast<uint32_t*>(&h);
}
// split (v0,v1) into packed bf16x2 hi and lo words (low 16 bits = v0)
__device__ __forceinline__ void pack_split(float v0, float v1, uint32_t& hi, uint32_t& lo){
    __nv_bfloat162 h = __floats2bfloat162_rn(v0, v1);
    hi = b2u(h);
    float r0 = v0 - __bfloat162float(h.x);
    float r1 = v1 - __bfloat162float(h.y);
    lo = b2u(__floats2bfloat162_rn(r0, r1));
}

// ---------------------------------------------------------------------------
// K0: presplit x, fused W (Q|K|V per head), Wo into packed bf16x2 hi/lo
// ---------------------------------------------------------------------------
__global__ void presplit(const float* __restrict__ x,
                         const float* __restrict__ Wq, const float* __restrict__ Wk,
                         const float* __restrict__ Wv, const float* __restrict__ Wo)
{
    const int nth = gridDim.x * blockDim.x;
    const int t0  = blockIdx.x * blockDim.x + threadIdx.x;
    // x: [4096][512 colpairs]
    for (int idx = t0; idx < MM*512; idx += nth) {
        int row = idx >> 9, cp = idx & 511;
        float2 v = *(const float2*)&x[(size_t)row * DD + 2*cp];
        pack_split(v.x, v.y, XH[idx], XL[idx]);
    }
    // fused W: [512 kpairs][2560 gn]
    for (int idx = t0; idx < 512*NQKV; idx += nth) {
        int kp = idx / NQKV, gn = idx - kp * NQKV;
        int h = gn / 160, off = gn - h * 160;
        int d0 = 2*kp, d1 = 2*kp + 1;
        float w0, w1;
        if (off < 64) {
            w0 = Wq[((size_t)h*DD + d0)*DKK + off];
            w1 = Wq[((size_t)h*DD + d1)*DKK + off];
        } else if (off < 128) {
            w0 = Wk[((size_t)h*DD + d0)*DKK + off - 64];
            w1 = Wk[((size_t)h*DD + d1)*DKK + off - 64];
        } else {
            w0 = Wv[((size_t)h*DD + d0)*DVV + off - 128];
            w1 = Wv[((size_t)h*DD + d1)*DVV + off - 128];
        }
        pack_split(w0, w1, WH[idx], WL[idx]);
    }
    // Wo: [256 kpairs][1024]
    for (int idx = t0; idx < 256*DD; idx += nth) {
        int kp = idx >> 10, n = idx & 1023;
        float w0 = Wo[(size_t)(2*kp)*DD + n];
        float w1 = Wo[(size_t)(2*kp + 1)*DD + n];
        pack_split(w0, w1, WOH[idx], WOL[idx]);
    }
}

// ---------------------------------------------------------------------------
// K2: repack q/k (colpair) and v (keypair) into bf16x2 hi/lo
// ---------------------------------------------------------------------------
__global__ void repack_qkv()
{
    const int nth = gridDim.x * blockDim.x;
    const int t0  = blockIdx.x * blockDim.x + threadIdx.x;
    for (int idx = t0; idx < BH*SS*32; idx += nth) {
        int row = idx >> 5, cp = idx & 31;
        float2 vq = *(const float2*)&g_q[(size_t)row * DKK + 2*cp];
        pack_split(vq.x, vq.y, QH[idx], QL[idx]);
        float2 vk = *(const float2*)&g_k[(size_t)row * DKK + 2*cp];
        pack_split(vk.x, vk.y, KH[idx], KL[idx]);
    }
    for (int idx = t0; idx < BH*512*32; idx += nth) {
        int bh = idx >> 14, rem = idx & 16383;
        int kp = rem >> 5, dv = rem & 31;
        size_t s0 = ((size_t)bh*SS + 2*kp) * DVV + dv;
        pack_split(g_v[s0], g_v[s0 + DVV], VH[idx], VL[idx]);
    }
}

// ---------------------------------------------------------------------------
// K1: QKV projection, 3-term bf16 split GEMM.
//  BM=128, BN=128, BK=32, 256 thr, warp tile 64x32. grid (32,20)
//  smem: per stage AH[128][20] AL BH[16][136] BL (u32); 2 stages = 75776 B
// ---------------------------------------------------------------------------
#define PA_STR 20
#define PB_STR 136
#define PA_SZ (128*PA_STR)     // 2560
#define PB_SZ (16*PB_STR)      // 2176
#define PSTG (2*PA_SZ + 2*PB_SZ)  // 9472 u32

__global__ void __launch_bounds__(256,1) proj_bf16(
    const float* __restrict__ bq, const float* __restrict__ bk,
    const float* __restrict__ bv)
{
    extern __shared__ uint32_t sm32[];
    const int tid  = threadIdx.x;
    const int lane = tid & 31, warp = tid >> 5;
    const int wm = warp & 1, wn = warp >> 1;
    const int r = lane & 3, g = lane >> 2;
    const int m0 = blockIdx.x * 128;
    const int n0 = blockIdx.y * 128;
    uint32_t sb = smem_u32(sm32);

    float acc[4][4][4];
    #pragma unroll
    for (int mt = 0; mt < 4; mt++)
        #pragma unroll
        for (int nt = 0; nt < 4; nt++)
            #pragma unroll
            for (int i = 0; i < 4; i++) acc[mt][nt][i] = 0.f;

    auto issue_load = [&](int s, int it) {
        uint32_t base = sb + (uint32_t)(s * PSTG) * 4u;
        // A hi/lo: 512 chunks each
        #pragma unroll
        for (int p = 0; p < 2; p++) {
            const uint32_t* src = p ? XL : XH;
            uint32_t dstb = base + (uint32_t)(p * PA_SZ) * 4u;
            #pragma unroll
            for (int i = 0; i < 2; i++) {
                int flat = tid + i * 256;
                int row = flat >> 2, c4 = (flat & 3) * 4;
                cp16(dstb + (uint32_t)(row * PA_STR + c4) * 4u,
                     &src[(size_t)(m0 + row) * 512 + it * 16 + c4]);
            }
        }
        // B hi/lo
        #pragma unroll
        for (int p = 0; p < 2; p++) {
            const uint32_t* src = p ? WL : WH;
            uint32_t dstb = base + (uint32_t)(2 * PA_SZ + p * PB_SZ) * 4u;
            #pragma unroll
            for (int i = 0; i < 2; i++) {
                int flat = tid + i * 256;
                int kp = flat >> 5, c = (flat & 31) * 4;
                cp16(dstb + (uint32_t)(kp * PB_STR + c) * 4u,
                     &src[(size_t)(it * 16 + kp) * NQKV + n0 + c]);
            }
        }
    };

    issue_load(0, 0);
    cp_commit();

    for (int it = 0; it < 32; it++) {
        if (it + 1 < 32) { issue_load((it + 1) & 1, it + 1); cp_commit(); cp_wait<1>(); }
        else             { cp_wait<0>(); }
        __syncthreads();

        const uint32_t* AHs = sm32 + (it & 1) * PSTG;
        const uint32_t* ALs = AHs + PA_SZ;
        const uint32_t* BHs = AHs + 2 * PA_SZ;
        const uint32_t* BLs = BHs + PB_SZ;

        #pragma unroll
        for (int kt = 0; kt < 2; kt++) {
            uint32_t ah[4][4], al[4][4], bh2[4][2], bl2[4][2];
            #pragma unroll
            for (int mt = 0; mt < 4; mt++) {
                int row = wm * 64 + mt * 16;
                int a0 = (row + g) * PA_STR + kt * 8 + r;
                int a1 = (row + g + 8) * PA_STR + kt * 8 + r;
                ah[mt][0] = AHs[a0]; ah[mt][1] = AHs[a1];
                ah[mt][2] = AHs[a0 + 4]; ah[mt][3] = AHs[a1 + 4];
                al[mt][0] = ALs[a0]; al[mt][1] = ALs[a1];
                al[mt][2] = ALs[a0 + 4]; al[mt][3] = ALs[a1 + 4];
            }
            #pragma unroll
            for (int nt = 0; nt < 4; nt++) {
                int col = wn * 32 + nt * 8 + g;
                int b0 = (kt * 8 + r) * PB_STR + col;
                int b1 = (kt * 8 + r + 4) * PB_STR + col;
                bh2[nt][0] = BHs[b0]; bh2[nt][1] = BHs[b1];
                bl2[nt][0] = BLs[b0]; bl2[nt][1] = BLs[b1];
            }
            #pragma unroll
            for (int mt = 0; mt < 4; mt++)
                #pragma unroll
                for (int nt = 0; nt < 4; nt++) {
                    mma_bf16(acc[mt][nt], ah[mt], bh2[nt]);
                    mma_bf16(acc[mt][nt], ah[mt], bl2[nt]);
                    mma_bf16(acc[mt][nt], al[mt], bh2[nt]);
                }
        }
        __syncthreads();
    }

    // epilogue: scatter to g_q/g_k/g_v with bias
    #pragma unroll
    for (int mt = 0; mt < 4; mt++) {
        int row0 = m0 + wm * 64 + mt * 16 + g;
        #pragma unroll
        for (int nt = 0; nt < 4; nt++) {
            int gn = n0 + wn * 32 + nt * 8 + 2 * r;
            int h = gn / 160, off = gn - h * 160;
            float bia0, bia1;
            float *dst0, *dst1;
            int b0_ = row0 >> 10, s0_ = row0 & 1023;
            int b1_ = (row0 + 8) >> 10, s1_ = (row0 + 8) & 1023;
            size_t bhs0, bhs1;
            if (off < 64) {
                bia0 = bq[h*DKK + off]; bia1 = bq[h*DKK + off + 1];
                bhs0 = ((size_t)(b0_*HH + h))*SS + s0_;
                bhs1 = ((size_t)(b1_*HH + h))*SS + s1_;
                dst0 = g_q + bhs0*DKK + off; dst1 = g_q + bhs1*DKK + off;
            } else if (off < 128) {
                int o = off - 64;
                bia0 = bk[h*DKK + o]; bia1 = bk[h*DKK + o + 1];
                bhs0 = ((size_t)(b0_*HH + h))*SS + s0_;
                bhs1 = ((size_t)(b1_*HH + h))*SS + s1_;
                dst0 = g_k + bhs0*DKK + o; dst1 = g_k + bhs1*DKK + o;
            } else {
                int o = off - 128;
                bia0 = bv[h*DVV + o]; bia1 = bv[h*DVV + o + 1];
                bhs0 = ((size_t)(b0_*HH + h))*SS + s0_;
                bhs1 = ((size_t)(b1_*HH + h))*SS + s1_;
                dst0 = g_v + bhs0*DVV + o; dst1 = g_v + bhs1*DVV + o;
            }
            *(float2*)dst0 = make_float2(acc[mt][nt][0] + bia0, acc[mt][nt][1] + bia1);
            *(float2*)dst1 = make_float2(acc[mt][nt][2] + bia0, acc[mt][nt][3] + bia1);
        }
    }
}

// ---------------------------------------------------------------------------
// K3: attention, bf16-split QK and PV. Block = (bh, 32-query tile), 256 thr.
// smem u32 layout: QHs[32][36] QLs | scf fp32 [32][1028] | K bufs (2 x hi/lo
// [64][36]) | V bufs (2 x hi/lo [32][36]) | sinv[32].  Total 196224 B.
// ---------------------------------------------------------------------------
#define QROWS 32
#define SC_STR 1028
#define T_STR 36
#define UQ_SZ (QROWS*T_STR)          // 1152
#define SC_SZ (QROWS*SC_STR)         // 32896
#define KBUF_SZ (2*64*T_STR)         // hi+lo = 4608
#define VBUF_SZ (2*32*T_STR)         // hi+lo = 2304

__global__ void __launch_bounds__(256,1) attn_bf16(float* __restrict__ wout)
{
    extern __shared__ uint32_t sm32[];
    uint32_t* uqh = sm32;
    uint32_t* uql = uqh + UQ_SZ;
    float*    scf = (float*)(sm32 + 2*UQ_SZ);
    uint32_t* kbase = sm32 + 2*UQ_SZ + SC_SZ;      // 2 bufs x KBUF_SZ
    uint32_t* vbase = kbase + 2*KBUF_SZ;           // 2 bufs x VBUF_SZ
    float*    sinv = (float*)(vbase + 2*VBUF_SZ);  // 32

    const int bh = blockIdx.x, qt = blockIdx.y;
    const int tid = threadIdx.x;
    const int lane = tid & 31, warp = tid >> 5;
    const int r = lane & 3, g = lane >> 2;
    const size_t base32 = (size_t)bh * SS + qt * QROWS;  // q row base
    const size_t kbase32 = (size_t)bh * SS;              // key row base

    uint32_t uqa = smem_u32(uqh), kba = smem_u32(kbase), vba = smem_u32(vbase);

    // prologue: Q tiles (hi/lo) + K chunk 0
    {
        int row = tid >> 3, c4 = (tid & 7) * 4;
        cp16(uqa + (uint32_t)(row * T_STR + c4) * 4u,
             &QH[(base32 + row) * 32 + c4]);
        cp16(uqa + (uint32_t)(UQ_SZ + row * T_STR + c4) * 4u,
             &QL[(base32 + row) * 32 + c4]);
    }
    #pragma unroll
    for (int p = 0; p < 2; p++) {
        const uint32_t* src = p ? KL : KH;
        #pragma unroll
        for (int i = 0; i < 2; i++) {
            int flat = tid + i * 256;
            int key = flat >> 3, c4 = (flat & 7) * 4;
            cp16(kba + (uint32_t)(p * (KBUF_SZ/2) + key * T_STR + c4) * 4u,
                 &src[(kbase32 + key) * 32 + c4]);
        }
    }
    cp_commit();

    uint32_t qah[2][4][4], qal[2][4][4];

    // ---- scores: 16 chunks of 64 keys ----
    for (int kc = 0; kc < 16; kc++) {
        if (kc + 1 < 16) {
            uint32_t dstb = kba + (uint32_t)(((kc + 1) & 1) * KBUF_SZ) * 4u;
            #pragma unroll
            for (int p = 0; p < 2; p++) {
                const uint32_t* src = p ? KL : KH;
                #pragma unroll
                for (int i = 0; i < 2; i++) {
                    int flat = tid + i * 256;
                    int key = flat >> 3, c4 = (flat & 7) * 4;
                    cp16(dstb + (uint32_t)(p * (KBUF_SZ/2) + key * T_STR + c4) * 4u,
                         &src[(kbase32 + (kc + 1) * 64 + key) * 32 + c4]);
                }
            }
            cp_commit(); cp_wait<1>();
        } else cp_wait<0>();
        __syncthreads();

        if (kc == 0) {
            #pragma unroll
            for (int mt = 0; mt < 2; mt++)
                #pragma unroll
                for (int kt = 0; kt < 4; kt++) {
                    int a0 = (mt*16 + g) * T_STR + kt*8 + r;
                    int a1 = (mt*16 + g + 8) * T_STR + kt*8 + r;
                    qah[mt][kt][0] = uqh[a0]; qah[mt][kt][1] = uqh[a1];
                    qah[mt][kt][2] = uqh[a0+4]; qah[mt][kt][3] = uqh[a1+4];
                    qal[mt][kt][0] = uql[a0]; qal[mt][kt][1] = uql[a1];
                    qal[mt][kt][2] = uql[a0+4]; qal[mt][kt][3] = uql[a1+4];
                }
        }

        const uint32_t* khb = kbase + (kc & 1) * KBUF_SZ;
        const uint32_t* klb = khb + KBUF_SZ/2;
        float accs[2][4] = {{0.f,0.f,0.f,0.f},{0.f,0.f,0.f,0.f}};
        #pragma unroll
        for (int kt = 0; kt < 4; kt++) {
            uint32_t bbh[2], bbl[2];
            int b0 = (warp*8 + g) * T_STR + kt*8 + r;
            bbh[0] = khb[b0]; bbh[1] = khb[b0 + 4];
            bbl[0] = klb[b0]; bbl[1] = klb[b0 + 4];
            #pragma unroll
            for (int mt = 0; mt < 2; mt++) {
                mma_bf16(accs[mt], qah[mt][kt], bbh);
                mma_bf16(accs[mt], qah[mt][kt], bbl);
                mma_bf16(accs[mt], qal[mt][kt], bbh);
            }
        }
        int keyb = kc * 64 + warp * 8;
        #pragma unroll
        for (int mt = 0; mt < 2; mt++) {
            float e0 = __expf(accs[mt][0] * 0.125f);
            float e1 = __expf(accs[mt][1] * 0.125f);
            float e2 = __expf(accs[mt][2] * 0.125f);
            float e3 = __expf(accs[mt][3] * 0.125f);
            int row = mt * 16 + g;
            *(float2*)(scf + row * SC_STR + keyb + 2*r)       = make_float2(e0, e1);
            *(float2*)(scf + (row + 8) * SC_STR + keyb + 2*r) = make_float2(e2, e3);
        }
        __syncthreads();
    }

    // prefetch V chunk 0 (hi/lo)
    {
        int kp = tid >> 3, c4 = (tid & 7) * 4;
        cp16(vba + (uint32_t)(kp * T_STR + c4) * 4u,
             &VH[((size_t)bh * 512 + kp) * 32 + c4]);
        cp16(vba + (uint32_t)(VBUF_SZ/2 + kp * T_STR + c4) * 4u,
             &VL[((size_t)bh * 512 + kp) * 32 + c4]);
    }
    cp_commit();

    // ---- row sums -> 1/sum ----
    {
        int row0 = warp * 4;
        #pragma unroll
        for (int rr = 0; rr < 4; rr++) {
            int row = row0 + rr;
            float s = 0.f;
            #pragma unroll
            for (int i = 0; i < 8; i++) {
                float4 v = *(const float4*)(scf + row * SC_STR + lane * 4 + i * 128);
                s += v.x + v.y + v.z + v.w;
            }
            #pragma unroll
            for (int o = 16; o; o >>= 1) s += __shfl_xor_sync(0xffffffffu, s, o);
            if (lane == 0) sinv[row] = 1.f / s;
        }
    }
    __syncthreads();

    // ---- stream normalized weights ----
    #pragma unroll 4
    for (int i = 0; i < 32; i++) {
        int f = tid + i * 256;
        int row = f >> 8, c4 = (f & 255) * 4;
        float4 v = *(const float4*)(scf + row * SC_STR + c4);
        float iv = sinv[row];
        v.x *= iv; v.y *= iv; v.z *= iv; v.w *= iv;
        *(float4*)(wout + ((kbase32 + qt * QROWS + row) << 10) + c4) = v;
    }

    // ---- PV: out[32][32], warp -> one m16n8 tile ----
    const int mtp = warp & 1, ntp = warp >> 1;
    float pacc[4] = {0.f, 0.f, 0.f, 0.f};
    for (int vc = 0; vc < 16; vc++) {
        if (vc + 1 < 16) {
            uint32_t dstb = vba + (uint32_t)(((vc + 1) & 1) * VBUF_SZ) * 4u;
            int kp = tid >> 3, c4 = (tid & 7) * 4;
            cp16(dstb + (uint32_t)(kp * T_STR + c4) * 4u,
                 &VH[((size_t)bh * 512 + (vc + 1) * 32 + kp) * 32 + c4]);
            cp16(dstb + (uint32_t)(VBUF_SZ/2 + kp * T_STR + c4) * 4u,
                 &VL[((size_t)bh * 512 + (vc + 1) * 32 + kp) * 32 + c4]);
            cp_commit(); cp_wait<1>();
        } else cp_wait<0>();
        __syncthreads();

        const uint32_t* vhb = vbase + (vc & 1) * VBUF_SZ;
        const uint32_t* vlb = vhb + VBUF_SZ/2;
        #pragma unroll
        for (int kt = 0; kt < 4; kt++) {
            // A = scores fp32 -> split bf16 in registers
            uint32_t ah[4], al[4];
            int row = mtp * 16;
            int kb = vc * 64 + kt * 16;
            float2 p0 = *(const float2*)(scf + (row + g)     * SC_STR + kb + 2*r);
            float2 p1 = *(const float2*)(scf + (row + g + 8) * SC_STR + kb + 2*r);
            float2 p2 = *(const float2*)(scf + (row + g)     * SC_STR + kb + 8 + 2*r);
            float2 p3 = *(const float2*)(scf + (row + g + 8) * SC_STR + kb + 8 + 2*r);
            pack_split(p0.x, p0.y, ah[0], al[0]);
            pack_split(p1.x, p1.y, ah[1], al[1]);
            pack_split(p2.x, p2.y, ah[2], al[2]);
            pack_split(p3.x, p3.y, ah[3], al[3]);
            uint32_t bbh[2], bbl[2];
            int b0 = (kt*8 + r) * T_STR + ntp*8 + g;
            int b1 = (kt*8 + r + 4) * T_STR + ntp*8 + g;
            bbh[0] = vhb[b0]; bbh[1] = vhb[b1];
            bbl[0] = vlb[b0]; bbl[1] = vlb[b1];
            mma_bf16(pacc, ah, bbh);
            mma_bf16(pacc, ah, bbl);
            mma_bf16(pacc, al, bbh);
        }
        __syncthreads();
    }

    // epilogue: normalize + write packed concat (hi/lo)
    {
        int row0 = mtp * 16 + g;
        float i0 = sinv[row0], i1 = sinv[row0 + 8];
        int b_ = bh >> 4, h = bh & 15;
        int cp = h * 16 + ntp * 4 + r;
        size_t r0 = (size_t)(b_ * SS + qt * QROWS + row0);
        uint32_t hi, lo;
        pack_split(pacc[0] * i0, pacc[1] * i0, hi, lo);
        GCH[r0 * 256 + cp] = hi; GCL[r0 * 256 + cp] = lo;
        pack_split(pacc[2] * i1, pacc[3] * i1, hi, lo);
        GCH[(r0 + 8) * 256 + cp] = hi; GCL[(r0 + 8) * 256 + cp] = lo;
    }
}

// ---------------------------------------------------------------------------
// K4: output projection, 3-term bf16 split. K=512 -> 16 iters. grid (32, 8)
// ---------------------------------------------------------------------------
__global__ void __launch_bounds__(256,1) outproj_bf16(
    const float* __restrict__ bo, float* __restrict__ out)
{
    extern __shared__ uint32_t sm32[];
    const int tid  = threadIdx.x;
    const int lane = tid & 31, warp = tid >> 5;
    const int wm = warp & 1, wn = warp >> 1;
    const int r = lane & 3, g = lane >> 2;
    const int m0 = blockIdx.x * 128;
    const int n0 = blockIdx.y * 128;
    uint32_t sb = smem_u32(sm32);

    float acc[4][4][4];
    #pragma unroll
    for (int mt = 0; mt < 4; mt++)
        #pragma unroll
        for (int nt = 0; nt < 4; nt++)
            #pragma unroll
            for (int i = 0; i < 4; i++) acc[mt][nt][i] = 0.f;

    auto issue_load = [&](int s, int it) {
        uint32_t base = sb + (uint32_t)(s * PSTG) * 4u;
        #pragma unroll
        for (int p = 0; p < 2; p++) {
            const uint32_t* src = p ? GCL : GCH;
            uint32_t dstb = base + (uint32_t)(p * PA_SZ) * 4u;
            #pragma unroll
            for (int i = 0; i < 2; i++) {
                int flat = tid + i * 256;
                int row = flat >> 2, c4 = (flat & 3) * 4;
                cp16(dstb + (uint32_t)(row * PA_STR + c4) * 4u,
                     &src[(size_t)(m0 + row) * 256 + it * 16 + c4]);
            }
        }
        #pragma unroll
        for (int p = 0; p < 2; p++) {
            const uint32_t* src = p ? WOL : WOH;
            uint32_t dstb = base + (uint32_t)(2 * PA_SZ + p * PB_SZ) * 4u;
            #pragma unroll
            for (int i = 0; i < 2; i++) {
                int flat = tid + i * 256;
                int kp = flat >> 5, c = (flat & 31) * 4;
                cp16(dstb + (uint32_t)(kp * PB_STR + c) * 4u,
                     &src[(size_t)(it * 16 + kp) * DD + n0 + c]);
            }
        }
    };

    issue_load(0, 0);
    cp_commit();

    for (int it = 0; it < 16; it++) {
        if (it + 1 < 16) { issue_load((it + 1) & 1, it + 1); cp_commit(); cp_wait<1>(); }
        else             { cp_wait<0>(); }
        __syncthreads();

        const uint32_t* AHs = sm32 + (it & 1) * PSTG;
        const uint32_t* ALs = AHs + PA_SZ;
        const uint32_t* BHs = AHs + 2 * PA_SZ;
        const uint32_t* BLs = BHs + PB_SZ;

        #pragma unroll
        for (int kt = 0; kt < 2; kt++) {
            uint32_t ah[4][4], al[4][4], bh2[4][2], bl2[4][2];
            #pragma unroll
            for (int mt = 0; mt < 4; mt++) {
                int row = wm * 64 + mt * 16;
                int a0 = (row + g) * PA_STR + kt * 8 + r;
                int a1 = (row + g + 8) * PA_STR + kt * 8 + r;
                ah[mt][0] = AHs[a0]; ah[mt][1] = AHs[a1];
                ah[mt][2] = AHs[a0 + 4]; ah[mt][3] = AHs[a1 + 4];
                al[mt][0] = ALs[a0]; al[mt][1] = ALs[a1];
                al[mt][2] = ALs[a0 + 4]; al[mt][3] = ALs[a1 + 4];
            }
            #pragma unroll
            for (int nt = 0; nt < 4; nt++) {
                int col = wn * 32 + nt * 8 + g;
                int b0 = (kt * 8 + r) * PB_STR + col;
                int b1 = (kt * 8 + r + 4) * PB_STR + col;
                bh2[nt][0] = BHs[b0]; bh2[nt][1] = BHs[b1];
                bl2[nt][0] = BLs[b0]; bl2[nt][1] = BLs[b1];
            }
            #pragma unroll
            for (int mt = 0; mt < 4; mt++)
                #pragma unroll
                for (int nt = 0; nt < 4; nt++) {
                    mma_bf16(acc[mt][nt], ah[mt], bh2[nt]);
                    mma_bf16(acc[mt][nt], ah[mt], bl2[nt]);
                    mma_bf16(acc[mt][nt], al[mt], bh2[nt]);
                }
        }
        __syncthreads();
    }

    #pragma unroll
    for (int mt = 0; mt < 4; mt++) {
        int row0 = m0 + wm * 64 + mt * 16 + g;
        #pragma unroll
        for (int nt = 0; nt < 4; nt++) {
            int gn = n0 + wn * 32 + nt * 8 + 2 * r;
            float bia0 = bo[gn], bia1 = bo[gn + 1];
            *(float2*)&out[(size_t)row0 * DD + gn] =
                make_float2(acc[mt][nt][0] + bia0, acc[mt][nt][1] + bia1);
            *(float2*)&out[(size_t)(row0 + 8) * DD + gn] =
                make_float2(acc[mt][nt][2] + bia0, acc[mt][nt][3] + bia1);
        }
    }
}

// ---------------------------------------------------------------------------
extern "C" void kernel_launch(void* const* d_in, const int* in_sizes, int n_in,
                              void* d_out, int out_size)
{
    const float* x  = (const float*)d_in[0];
    const float* Wq = (const float*)d_in[1];
    const float* bq = (const float*)d_in[2];
    const float* Wk = (const float*)d_in[3];
    const float* bk = (const float*)d_in[4];
    const float* Wv = (const float*)d_in[5];
    const float* bv = (const float*)d_in[6];
    const float* Wo = (const float*)d_in[7];
    const float* bo = (const float*)d_in[8];

    float* out  = (float*)d_out;
    float* wptr = out + (size_t)BB * SS * DD;   // weights after output

    const int gemm_smem = 2 * PSTG * (int)sizeof(uint32_t);   // 75776
    const int attn_smem = (2*UQ_SZ + SC_SZ + 2*KBUF_SZ + 2*VBUF_SZ + 32)
                          * (int)sizeof(uint32_t);            // 196224

    cudaFuncSetAttribute(proj_bf16,    cudaFuncAttributeMaxDynamicSharedMemorySize, gemm_smem);
    cudaFuncSetAttribute(outproj_bf16, cudaFuncAttributeMaxDynamicSharedMemorySize, gemm_smem);
    cudaFuncSetAttribute(attn_bf16,    cudaFuncAttributeMaxDynamicSharedMemorySize, attn_smem);

    presplit<<<512, 256>>>(x, Wq, Wk, Wv, Wo);
    proj_bf16<<<dim3(MM/128, NQKV/128), 256, gemm_smem>>>(bq, bk, bv);
    repack_qkv<<<512, 256>>>();
    attn_bf16<<<dim3(BH, SS/QROWS), 256, attn_smem>>>(wptr);
    outproj_bf16<<<dim3(MM/128, DD/128), 256, gemm_smem>>>(bo, out);
}

// round 5
// speedup vs baseline: 2.8407x; 1.0306x over previous
#include <cuda_runtime.h>
#include <cuda_bf16.h>
#include <cstdint>

#define BB 4
#define SS 1024
#define DD 1024
#define HH 16
#define DKK 64
#define DVV 32
#define BH (BB*HH)          // 64
#define MM (BB*SS)          // 4096
#define CDIM (HH*DVV)       // 512
#define NQKV (HH*160)       // 2560

// fp32 intermediates
__device__ float g_q[BH*SS*DKK];
__device__ float g_k[BH*SS*DKK];
__device__ float g_v[BH*SS*DVV];

// packed bf16x2 split operands (hi/lo)
__device__ uint32_t XH[MM*512],  XL[MM*512];       // x colpair-packed [4096][512]
__device__ uint32_t WH[512*NQKV], WL[512*NQKV];    // fused W kpair-packed [512][2560]
__device__ uint32_t WOH[256*DD],  WOL[256*DD];     // Wo kpair-packed [256][1024]
__device__ uint32_t QH[BH*SS*32], QL[BH*SS*32];    // q colpair-packed [bh*1024][32]
__device__ uint32_t KH[BH*SS*32], KL[BH*SS*32];    // k colpair-packed
__device__ uint32_t VH[BH*512*32], VL[BH*512*32];  // v keypair-packed [bh][512][32]
__device__ uint32_t GCH[MM*256],  GCL[MM*256];     // concat colpair-packed [4096][256]

// ---------------------------------------------------------------------------
// helpers
// ---------------------------------------------------------------------------
__device__ __forceinline__ uint32_t smem_u32(const void* p){
    return (uint32_t)__cvta_generic_to_shared(p);
}
__device__ __forceinline__ void cp16(uint32_t dst, const void* src){
    asm volatile("cp.async.cg.shared.global [%0], [%1], 16;\n" :: "r"(dst), "l"(src));
}
__device__ __forceinline__ void cp_commit(){ asm volatile("cp.async.commit_group;\n"); }
template<int N> __device__ __forceinline__ void cp_wait(){
    asm volatile("cp.async.wait_group %0;\n" :: "n"(N));
}
__device__ __forceinline__ void mma_bf16(float* d, const uint32_t* a, const uint32_t* b){
    asm volatile(
      "mma.sync.aligned.m16n8k16.row.col.f32.bf16.bf16.f32 "
      "{%0,%1,%2,%3},{%4,%5,%6,%7},{%8,%9},{%0,%1,%2,%3};\n"
      : "+f"(d[0]),"+f"(d[1]),"+f"(d[2]),"+f"(d[3])
      : "r"(a[0]),"r"(a[1]),"r"(a[2]),"r"(a[3]),"r"(b[0]),"r"(b[1]));
}
__device__ __forceinline__ uint32_t b2u(__nv_bfloat162 h){
    return *reinterpret_cast<uint32_t*>(&h);
}
__device__ __forceinline__ float2 u2f2(uint32_t u){
    __nv_bfloat162 h = *reinterpret_cast<__nv_bfloat162*>(&u);
    return __bfloat1622float2(h);
}
// split (v0,v1) into packed bf16x2 hi and lo words (low 16 bits = v0)
__device__ __forceinline__ void pack_split(float v0, float v1, uint32_t& hi, uint32_t& lo){
    __nv_bfloat162 h = __floats2bfloat162_rn(v0, v1);
    hi = b2u(h);
    float r0 = v0 - __bfloat162float(h.x);
    float r1 = v1 - __bfloat162float(h.y);
    lo = b2u(__floats2bfloat162_rn(r0, r1));
}

// ---------------------------------------------------------------------------
// K0: presplit x, fused W (Q|K|V per head), Wo into packed bf16x2 hi/lo
// ---------------------------------------------------------------------------
__global__ void presplit(const float* __restrict__ x,
                         const float* __restrict__ Wq, const float* __restrict__ Wk,
                         const float* __restrict__ Wv, const float* __restrict__ Wo)
{
    const int nth = gridDim.x * blockDim.x;
    const int t0  = blockIdx.x * blockDim.x + threadIdx.x;
    for (int idx = t0; idx < MM*512; idx += nth) {
        int row = idx >> 9, cp = idx & 511;
        float2 v = *(const float2*)&x[(size_t)row * DD + 2*cp];
        pack_split(v.x, v.y, XH[idx], XL[idx]);
    }
    for (int idx = t0; idx < 512*NQKV; idx += nth) {
        int kp = idx / NQKV, gn = idx - kp * NQKV;
        int h = gn / 160, off = gn - h * 160;
        int d0 = 2*kp, d1 = 2*kp + 1;
        float w0, w1;
        if (off < 64) {
            w0 = Wq[((size_t)h*DD + d0)*DKK + off];
            w1 = Wq[((size_t)h*DD + d1)*DKK + off];
        } else if (off < 128) {
            w0 = Wk[((size_t)h*DD + d0)*DKK + off - 64];
            w1 = Wk[((size_t)h*DD + d1)*DKK + off - 64];
        } else {
            w0 = Wv[((size_t)h*DD + d0)*DVV + off - 128];
            w1 = Wv[((size_t)h*DD + d1)*DVV + off - 128];
        }
        pack_split(w0, w1, WH[idx], WL[idx]);
    }
    for (int idx = t0; idx < 256*DD; idx += nth) {
        int kp = idx >> 10, n = idx & 1023;
        float w0 = Wo[(size_t)(2*kp)*DD + n];
        float w1 = Wo[(size_t)(2*kp + 1)*DD + n];
        pack_split(w0, w1, WOH[idx], WOL[idx]);
    }
}

// ---------------------------------------------------------------------------
// K2: repack q/k (colpair) and v (keypair) into bf16x2 hi/lo
// ---------------------------------------------------------------------------
__global__ void repack_qkv()
{
    const int nth = gridDim.x * blockDim.x;
    const int t0  = blockIdx.x * blockDim.x + threadIdx.x;
    for (int idx = t0; idx < BH*SS*32; idx += nth) {
        int row = idx >> 5, cp = idx & 31;
        float2 vq = *(const float2*)&g_q[(size_t)row * DKK + 2*cp];
        pack_split(vq.x, vq.y, QH[idx], QL[idx]);
        float2 vk = *(const float2*)&g_k[(size_t)row * DKK + 2*cp];
        pack_split(vk.x, vk.y, KH[idx], KL[idx]);
    }
    for (int idx = t0; idx < BH*512*32; idx += nth) {
        int bh = idx >> 14, rem = idx & 16383;
        int kp = rem >> 5, dv = rem & 31;
        size_t s0 = ((size_t)bh*SS + 2*kp) * DVV + dv;
        pack_split(g_v[s0], g_v[s0 + DVV], VH[idx], VL[idx]);
    }
}

// ---------------------------------------------------------------------------
// K1: QKV projection, 3-term bf16 split GEMM.
//  BM=128, BN=128, BK=32, 256 thr, warp tile 64x32. grid (32,20)
// ---------------------------------------------------------------------------
#define PA_STR 20
#define PB_STR 136
#define PA_SZ (128*PA_STR)     // 2560
#define PB_SZ (16*PB_STR)      // 2176
#define PSTG (2*PA_SZ + 2*PB_SZ)  // 9472 u32

__global__ void __launch_bounds__(256,1) proj_bf16(
    const float* __restrict__ bq, const float* __restrict__ bk,
    const float* __restrict__ bv)
{
    extern __shared__ uint32_t sm32[];
    const int tid  = threadIdx.x;
    const int lane = tid & 31, warp = tid >> 5;
    const int wm = warp & 1, wn = warp >> 1;
    const int r = lane & 3, g = lane >> 2;
    const int m0 = blockIdx.x * 128;
    const int n0 = blockIdx.y * 128;
    uint32_t sb = smem_u32(sm32);

    float acc[4][4][4];
    #pragma unroll
    for (int mt = 0; mt < 4; mt++)
        #pragma unroll
        for (int nt = 0; nt < 4; nt++)
            #pragma unroll
            for (int i = 0; i < 4; i++) acc[mt][nt][i] = 0.f;

    auto issue_load = [&](int s, int it) {
        uint32_t base = sb + (uint32_t)(s * PSTG) * 4u;
        #pragma unroll
        for (int p = 0; p < 2; p++) {
            const uint32_t* src = p ? XL : XH;
            uint32_t dstb = base + (uint32_t)(p * PA_SZ) * 4u;
            #pragma unroll
            for (int i = 0; i < 2; i++) {
                int flat = tid + i * 256;
                int row = flat >> 2, c4 = (flat & 3) * 4;
                cp16(dstb + (uint32_t)(row * PA_STR + c4) * 4u,
                     &src[(size_t)(m0 + row) * 512 + it * 16 + c4]);
            }
        }
        #pragma unroll
        for (int p = 0; p < 2; p++) {
            const uint32_t* src = p ? WL : WH;
            uint32_t dstb = base + (uint32_t)(2 * PA_SZ + p * PB_SZ) * 4u;
            #pragma unroll
            for (int i = 0; i < 2; i++) {
                int flat = tid + i * 256;
                int kp = flat >> 5, c = (flat & 31) * 4;
                cp16(dstb + (uint32_t)(kp * PB_STR + c) * 4u,
                     &src[(size_t)(it * 16 + kp) * NQKV + n0 + c]);
            }
        }
    };

    issue_load(0, 0);
    cp_commit();

    for (int it = 0; it < 32; it++) {
        if (it + 1 < 32) { issue_load((it + 1) & 1, it + 1); cp_commit(); cp_wait<1>(); }
        else             { cp_wait<0>(); }
        __syncthreads();

        const uint32_t* AHs = sm32 + (it & 1) * PSTG;
        const uint32_t* ALs = AHs + PA_SZ;
        const uint32_t* BHs = AHs + 2 * PA_SZ;
        const uint32_t* BLs = BHs + PB_SZ;

        #pragma unroll
        for (int kt = 0; kt < 2; kt++) {
            uint32_t ah[4][4], al[4][4], bh2[4][2], bl2[4][2];
            #pragma unroll
            for (int mt = 0; mt < 4; mt++) {
                int row = wm * 64 + mt * 16;
                int a0 = (row + g) * PA_STR + kt * 8 + r;
                int a1 = (row + g + 8) * PA_STR + kt * 8 + r;
                ah[mt][0] = AHs[a0]; ah[mt][1] = AHs[a1];
                ah[mt][2] = AHs[a0 + 4]; ah[mt][3] = AHs[a1 + 4];
                al[mt][0] = ALs[a0]; al[mt][1] = ALs[a1];
                al[mt][2] = ALs[a0 + 4]; al[mt][3] = ALs[a1 + 4];
            }
            #pragma unroll
            for (int nt = 0; nt < 4; nt++) {
                int col = wn * 32 + nt * 8 + g;
                int b0 = (kt * 8 + r) * PB_STR + col;
                int b1 = (kt * 8 + r + 4) * PB_STR + col;
                bh2[nt][0] = BHs[b0]; bh2[nt][1] = BHs[b1];
                bl2[nt][0] = BLs[b0]; bl2[nt][1] = BLs[b1];
            }
            #pragma unroll
            for (int mt = 0; mt < 4; mt++)
                #pragma unroll
                for (int nt = 0; nt < 4; nt++) {
                    mma_bf16(acc[mt][nt], ah[mt], bh2[nt]);
                    mma_bf16(acc[mt][nt], ah[mt], bl2[nt]);
                    mma_bf16(acc[mt][nt], al[mt], bh2[nt]);
                }
        }
        __syncthreads();
    }

    #pragma unroll
    for (int mt = 0; mt < 4; mt++) {
        int row0 = m0 + wm * 64 + mt * 16 + g;
        #pragma unroll
        for (int nt = 0; nt < 4; nt++) {
            int gn = n0 + wn * 32 + nt * 8 + 2 * r;
            int h = gn / 160, off = gn - h * 160;
            float bia0, bia1;
            float *dst0, *dst1;
            int b0_ = row0 >> 10, s0_ = row0 & 1023;
            int b1_ = (row0 + 8) >> 10, s1_ = (row0 + 8) & 1023;
            size_t bhs0, bhs1;
            if (off < 64) {
                bia0 = bq[h*DKK + off]; bia1 = bq[h*DKK + off + 1];
                bhs0 = ((size_t)(b0_*HH + h))*SS + s0_;
                bhs1 = ((size_t)(b1_*HH + h))*SS + s1_;
                dst0 = g_q + bhs0*DKK + off; dst1 = g_q + bhs1*DKK + off;
            } else if (off < 128) {
                int o = off - 64;
                bia0 = bk[h*DKK + o]; bia1 = bk[h*DKK + o + 1];
                bhs0 = ((size_t)(b0_*HH + h))*SS + s0_;
                bhs1 = ((size_t)(b1_*HH + h))*SS + s1_;
                dst0 = g_k + bhs0*DKK + o; dst1 = g_k + bhs1*DKK + o;
            } else {
                int o = off - 128;
                bia0 = bv[h*DVV + o]; bia1 = bv[h*DVV + o + 1];
                bhs0 = ((size_t)(b0_*HH + h))*SS + s0_;
                bhs1 = ((size_t)(b1_*HH + h))*SS + s1_;
                dst0 = g_v + bhs0*DVV + o; dst1 = g_v + bhs1*DVV + o;
            }
            *(float2*)dst0 = make_float2(acc[mt][nt][0] + bia0, acc[mt][nt][1] + bia1);
            *(float2*)dst1 = make_float2(acc[mt][nt][2] + bia0, acc[mt][nt][3] + bia1);
        }
    }
}

// ---------------------------------------------------------------------------
// K3: attention v2. Block = (bh, 32-query tile), 256 thr.
//  - 3 independent accumulators per split term (hh/hl/lh) in QK and PV
//  - scores stored PRE-SPLIT as packed bf16x2 hi/lo u32 [32][516] each;
//    QK D-fragment col pairs (2r,2r+1) == PV A-fragment pair layout, so
//    PV A operands are direct LDS.32 (no pack_split in mainloop)
//  - weights out = (hi + lo) * sinv
// smem u32: uqh|uql [32][36]x2 | sch|scl [32][516]x2 | K bufs 2x(hi/lo [64][36])
//           | V bufs 2x(hi/lo [32][36]) | sinv[32]  = 49184 u32 = 196736 B
// ---------------------------------------------------------------------------
#define QROWS 32
#define SC2_STR 516
#define T_STR 36
#define UQ_SZ (QROWS*T_STR)          // 1152
#define SCH_SZ (QROWS*SC2_STR)       // 16512
#define KBUF_SZ (2*64*T_STR)         // hi+lo = 4608
#define VBUF_SZ (2*32*T_STR)         // hi+lo = 2304

__global__ void __launch_bounds__(256,1) attn_bf16(float* __restrict__ wout)
{
    extern __shared__ uint32_t sm32[];
    uint32_t* uqh = sm32;
    uint32_t* uql = uqh + UQ_SZ;
    uint32_t* sch = sm32 + 2*UQ_SZ;
    uint32_t* scl = sch + SCH_SZ;
    uint32_t* kbase = sm32 + 2*UQ_SZ + 2*SCH_SZ;
    uint32_t* vbase = kbase + 2*KBUF_SZ;
    float*    sinv = (float*)(vbase + 2*VBUF_SZ);

    const int bh = blockIdx.x, qt = blockIdx.y;
    const int tid = threadIdx.x;
    const int lane = tid & 31, warp = tid >> 5;
    const int r = lane & 3, g = lane >> 2;
    const size_t base32 = (size_t)bh * SS + qt * QROWS;
    const size_t kbase32 = (size_t)bh * SS;

    uint32_t uqa = smem_u32(uqh), kba = smem_u32(kbase), vba = smem_u32(vbase);

    // prologue: Q tiles (hi/lo) + K chunk 0
    {
        int row = tid >> 3, c4 = (tid & 7) * 4;
        cp16(uqa + (uint32_t)(row * T_STR + c4) * 4u,
             &QH[(base32 + row) * 32 + c4]);
        cp16(uqa + (uint32_t)(UQ_SZ + row * T_STR + c4) * 4u,
             &QL[(base32 + row) * 32 + c4]);
    }
    #pragma unroll
    for (int p = 0; p < 2; p++) {
        const uint32_t* src = p ? KL : KH;
        #pragma unroll
        for (int i = 0; i < 2; i++) {
            int flat = tid + i * 256;
            int key = flat >> 3, c4 = (flat & 7) * 4;
            cp16(kba + (uint32_t)(p * (KBUF_SZ/2) + key * T_STR + c4) * 4u,
                 &src[(kbase32 + key) * 32 + c4]);
        }
    }
    cp_commit();

    uint32_t qah[2][4][4], qal[2][4][4];

    // ---- scores: 16 chunks of 64 keys ----
    for (int kc = 0; kc < 16; kc++) {
        if (kc + 1 < 16) {
            uint32_t dstb = kba + (uint32_t)(((kc + 1) & 1) * KBUF_SZ) * 4u;
            #pragma unroll
            for (int p = 0; p < 2; p++) {
                const uint32_t* src = p ? KL : KH;
                #pragma unroll
                for (int i = 0; i < 2; i++) {
                    int flat = tid + i * 256;
                    int key = flat >> 3, c4 = (flat & 7) * 4;
                    cp16(dstb + (uint32_t)(p * (KBUF_SZ/2) + key * T_STR + c4) * 4u,
                         &src[(kbase32 + (kc + 1) * 64 + key) * 32 + c4]);
                }
            }
            cp_commit(); cp_wait<1>();
        } else cp_wait<0>();
        __syncthreads();

        if (kc == 0) {
            #pragma unroll
            for (int mt = 0; mt < 2; mt++)
                #pragma unroll
                for (int kt = 0; kt < 4; kt++) {
                    int a0 = (mt*16 + g) * T_STR + kt*8 + r;
                    int a1 = (mt*16 + g + 8) * T_STR + kt*8 + r;
                    qah[mt][kt][0] = uqh[a0]; qah[mt][kt][1] = uqh[a1];
                    qah[mt][kt][2] = uqh[a0+4]; qah[mt][kt][3] = uqh[a1+4];
                    qal[mt][kt][0] = uql[a0]; qal[mt][kt][1] = uql[a1];
                    qal[mt][kt][2] = uql[a0+4]; qal[mt][kt][3] = uql[a1+4];
                }
        }

        const uint32_t* khb = kbase + (kc & 1) * KBUF_SZ;
        const uint32_t* klb = khb + KBUF_SZ/2;
        // 6 independent accumulator chains (2 mt x 3 split terms)
        float hh[2][4], hl[2][4], lh[2][4];
        #pragma unroll
        for (int mt = 0; mt < 2; mt++)
            #pragma unroll
            for (int i = 0; i < 4; i++) { hh[mt][i]=0.f; hl[mt][i]=0.f; lh[mt][i]=0.f; }

        #pragma unroll
        for (int kt = 0; kt < 4; kt++) {
            uint32_t bbh[2], bbl[2];
            int b0 = (warp*8 + g) * T_STR + kt*8 + r;
            bbh[0] = khb[b0]; bbh[1] = khb[b0 + 4];
            bbl[0] = klb[b0]; bbl[1] = klb[b0 + 4];
            mma_bf16(hh[0], qah[0][kt], bbh);
            mma_bf16(hh[1], qah[1][kt], bbh);
            mma_bf16(hl[0], qah[0][kt], bbl);
            mma_bf16(hl[1], qah[1][kt], bbl);
            mma_bf16(lh[0], qal[0][kt], bbh);
            mma_bf16(lh[1], qal[1][kt], bbh);
        }
        int keyb2 = kc * 32 + warp * 4;   // colpair index of this warp's 8 keys
        #pragma unroll
        for (int mt = 0; mt < 2; mt++) {
            float s0 = (hh[mt][0] + hl[mt][0] + lh[mt][0]) * 0.125f;
            float s1 = (hh[mt][1] + hl[mt][1] + lh[mt][1]) * 0.125f;
            float s2 = (hh[mt][2] + hl[mt][2] + lh[mt][2]) * 0.125f;
            float s3 = (hh[mt][3] + hl[mt][3] + lh[mt][3]) * 0.125f;
            float e0 = __expf(s0), e1 = __expf(s1), e2 = __expf(s2), e3 = __expf(s3);
            int row = mt * 16 + g;
            uint32_t hi, lo;
            pack_split(e0, e1, hi, lo);
            sch[row * SC2_STR + keyb2 + r] = hi;
            scl[row * SC2_STR + keyb2 + r] = lo;
            pack_split(e2, e3, hi, lo);
            sch[(row + 8) * SC2_STR + keyb2 + r] = hi;
            scl[(row + 8) * SC2_STR + keyb2 + r] = lo;
        }
        __syncthreads();
    }

    // prefetch V chunk 0 (hi/lo)
    {
        int kp = tid >> 3, c4 = (tid & 7) * 4;
        cp16(vba + (uint32_t)(kp * T_STR + c4) * 4u,
             &VH[((size_t)bh * 512 + kp) * 32 + c4]);
        cp16(vba + (uint32_t)(VBUF_SZ/2 + kp * T_STR + c4) * 4u,
             &VL[((size_t)bh * 512 + kp) * 32 + c4]);
    }
    cp_commit();

    // ---- row sums (hi+lo) -> 1/sum ----
    {
        int row0 = warp * 4;
        #pragma unroll
        for (int rr = 0; rr < 4; rr++) {
            int row = row0 + rr;
            float s = 0.f;
            #pragma unroll
            for (int i = 0; i < 4; i++) {
                uint4 h4 = *(const uint4*)(sch + row * SC2_STR + lane * 4 + i * 128);
                uint4 l4 = *(const uint4*)(scl + row * SC2_STR + lane * 4 + i * 128);
                float2 a0 = u2f2(h4.x), a1 = u2f2(h4.y), a2 = u2f2(h4.z), a3 = u2f2(h4.w);
                float2 c0 = u2f2(l4.x), c1 = u2f2(l4.y), c2 = u2f2(l4.z), c3 = u2f2(l4.w);
                s += a0.x + a0.y + a1.x + a1.y + a2.x + a2.y + a3.x + a3.y;
                s += c0.x + c0.y + c1.x + c1.y + c2.x + c2.y + c3.x + c3.y;
            }
            #pragma unroll
            for (int o = 16; o; o >>= 1) s += __shfl_xor_sync(0xffffffffu, s, o);
            if (lane == 0) sinv[row] = 1.f / s;
        }
    }
    __syncthreads();

    // ---- stream normalized weights: w = (hi + lo) * sinv ----
    #pragma unroll 4
    for (int i = 0; i < 32; i++) {
        int f = tid + i * 256;
        int row = f >> 8, cpp = (f & 255) * 2;
        uint2 h2 = *(const uint2*)(sch + row * SC2_STR + cpp);
        uint2 l2 = *(const uint2*)(scl + row * SC2_STR + cpp);
        float iv = sinv[row];
        float2 w0 = u2f2(h2.x), w1 = u2f2(h2.y);
        float2 d0 = u2f2(l2.x), d1 = u2f2(l2.y);
        float4 v;
        v.x = (w0.x + d0.x) * iv;
        v.y = (w0.y + d0.y) * iv;
        v.z = (w1.x + d1.x) * iv;
        v.w = (w1.y + d1.y) * iv;
        *(float4*)(wout + ((kbase32 + qt * QROWS + row) << 10) + cpp * 2) = v;
    }

    // ---- PV: out[32][32], warp -> one m16n8 tile; 3 independent acc chains ----
    const int mtp = warp & 1, ntp = warp >> 1;
    float phh[4] = {0,0,0,0}, phl[4] = {0,0,0,0}, plh[4] = {0,0,0,0};
    for (int vc = 0; vc < 16; vc++) {
        if (vc + 1 < 16) {
            uint32_t dstb = vba + (uint32_t)(((vc + 1) & 1) * VBUF_SZ) * 4u;
            int kp = tid >> 3, c4 = (tid & 7) * 4;
            cp16(dstb + (uint32_t)(kp * T_STR + c4) * 4u,
                 &VH[((size_t)bh * 512 + (vc + 1) * 32 + kp) * 32 + c4]);
            cp16(dstb + (uint32_t)(VBUF_SZ/2 + kp * T_STR + c4) * 4u,
                 &VL[((size_t)bh * 512 + (vc + 1) * 32 + kp) * 32 + c4]);
            cp_commit(); cp_wait<1>();
        } else cp_wait<0>();
        __syncthreads();

        const uint32_t* vhb = vbase + (vc & 1) * VBUF_SZ;
        const uint32_t* vlb = vhb + VBUF_SZ/2;
        const int row = mtp * 16;
        #pragma unroll
        for (int kt = 0; kt < 4; kt++) {
            int kb2 = vc * 32 + kt * 8;
            uint32_t ah[4], al[4];
            int a0 = (row + g) * SC2_STR + kb2 + r;
            int a1 = (row + g + 8) * SC2_STR + kb2 + r;
            ah[0] = sch[a0];     ah[1] = sch[a1];
            ah[2] = sch[a0 + 4]; ah[3] = sch[a1 + 4];
            al[0] = scl[a0];     al[1] = scl[a1];
            al[2] = scl[a0 + 4]; al[3] = scl[a1 + 4];
            uint32_t bbh[2], bbl[2];
            int b0 = (kt*8 + r) * T_STR + ntp*8 + g;
            int b1 = (kt*8 + r + 4) * T_STR + ntp*8 + g;
            bbh[0] = vhb[b0]; bbh[1] = vhb[b1];
            bbl[0] = vlb[b0]; bbl[1] = vlb[b1];
            mma_bf16(phh, ah, bbh);
            mma_bf16(phl, ah, bbl);
            mma_bf16(plh, al, bbh);
        }
        __syncthreads();
    }

    // epilogue: combine terms, normalize, write packed concat (hi/lo)
    {
        float pacc[4];
        #pragma unroll
        for (int i = 0; i < 4; i++) pacc[i] = phh[i] + phl[i] + plh[i];
        int row0 = mtp * 16 + g;
        float i0 = sinv[row0], i1 = sinv[row0 + 8];
        int b_ = bh >> 4, h = bh & 15;
        int cp = h * 16 + ntp * 4 + r;
        size_t r0 = (size_t)(b_ * SS + qt * QROWS + row0);
        uint32_t hi, lo;
        pack_split(pacc[0] * i0, pacc[1] * i0, hi, lo);
        GCH[r0 * 256 + cp] = hi; GCL[r0 * 256 + cp] = lo;
        pack_split(pacc[2] * i1, pacc[3] * i1, hi, lo);
        GCH[(r0 + 8) * 256 + cp] = hi; GCL[(r0 + 8) * 256 + cp] = lo;
    }
}

// ---------------------------------------------------------------------------
// K4: output projection, 3-term bf16 split. K=512 -> 16 iters. grid (32, 8)
// ---------------------------------------------------------------------------
__global__ void __launch_bounds__(256,1) outproj_bf16(
    const float* __restrict__ bo, float* __restrict__ out)
{
    extern __shared__ uint32_t sm32[];
    const int tid  = threadIdx.x;
    const int lane = tid & 31, warp = tid >> 5;
    const int wm = warp & 1, wn = warp >> 1;
    const int r = lane & 3, g = lane >> 2;
    const int m0 = blockIdx.x * 128;
    const int n0 = blockIdx.y * 128;
    uint32_t sb = smem_u32(sm32);

    float acc[4][4][4];
    #pragma unroll
    for (int mt = 0; mt < 4; mt++)
        #pragma unroll
        for (int nt = 0; nt < 4; nt++)
            #pragma unroll
            for (int i = 0; i < 4; i++) acc[mt][nt][i] = 0.f;

    auto issue_load = [&](int s, int it) {
        uint32_t base = sb + (uint32_t)(s * PSTG) * 4u;
        #pragma unroll
        for (int p = 0; p < 2; p++) {
            const uint32_t* src = p ? GCL : GCH;
            uint32_t dstb = base + (uint32_t)(p * PA_SZ) * 4u;
            #pragma unroll
            for (int i = 0; i < 2; i++) {
                int flat = tid + i * 256;
                int row = flat >> 2, c4 = (flat & 3) * 4;
                cp16(dstb + (uint32_t)(row * PA_STR + c4) * 4u,
                     &src[(size_t)(m0 + row) * 256 + it * 16 + c4]);
            }
        }
        #pragma unroll
        for (int p = 0; p < 2; p++) {
            const uint32_t* src = p ? WOL : WOH;
            uint32_t dstb = base + (uint32_t)(2 * PA_SZ + p * PB_SZ) * 4u;
            #pragma unroll
            for (int i = 0; i < 2; i++) {
                int flat = tid + i * 256;
                int kp = flat >> 5, c = (flat & 31) * 4;
                cp16(dstb + (uint32_t)(kp * PB_STR + c) * 4u,
                     &src[(size_t)(it * 16 + kp) * DD + n0 + c]);
            }
        }
    };

    issue_load(0, 0);
    cp_commit();

    for (int it = 0; it < 16; it++) {
        if (it + 1 < 16) { issue_load((it + 1) & 1, it + 1); cp_commit(); cp_wait<1>(); }
        else             { cp_wait<0>(); }
        __syncthreads();

        const uint32_t* AHs = sm32 + (it & 1) * PSTG;
        const uint32_t* ALs = AHs + PA_SZ;
        const uint32_t* BHs = AHs + 2 * PA_SZ;
        const uint32_t* BLs = BHs + PB_SZ;

        #pragma unroll
        for (int kt = 0; kt < 2; kt++) {
            uint32_t ah[4][4], al[4][4], bh2[4][2], bl2[4][2];
            #pragma unroll
            for (int mt = 0; mt < 4; mt++) {
                int row = wm * 64 + mt * 16;
                int a0 = (row + g) * PA_STR + kt * 8 + r;
                int a1 = (row + g + 8) * PA_STR + kt * 8 + r;
                ah[mt][0] = AHs[a0]; ah[mt][1] = AHs[a1];
                ah[mt][2] = AHs[a0 + 4]; ah[mt][3] = AHs[a1 + 4];
                al[mt][0] = ALs[a0]; al[mt][1] = ALs[a1];
                al[mt][2] = ALs[a0 + 4]; al[mt][3] = ALs[a1 + 4];
            }
            #pragma unroll
            for (int nt = 0; nt < 4; nt++) {
                int col = wn * 32 + nt * 8 + g;
                int b0 = (kt * 8 + r) * PB_STR + col;
                int b1 = (kt * 8 + r + 4) * PB_STR + col;
                bh2[nt][0] = BHs[b0]; bh2[nt][1] = BHs[b1];
                bl2[nt][0] = BLs[b0]; bl2[nt][1] = BLs[b1];
            }
            #pragma unroll
            for (int mt = 0; mt < 4; mt++)
                #pragma unroll
                for (int nt = 0; nt < 4; nt++) {
                    mma_bf16(acc[mt][nt], ah[mt], bh2[nt]);
                    mma_bf16(acc[mt][nt], ah[mt], bl2[nt]);
                    mma_bf16(acc[mt][nt], al[mt], bh2[nt]);
                }
        }
        __syncthreads();
    }

    #pragma unroll
    for (int mt = 0; mt < 4; mt++) {
        int row0 = m0 + wm * 64 + mt * 16 + g;
        #pragma unroll
        for (int nt = 0; nt < 4; nt++) {
            int gn = n0 + wn * 32 + nt * 8 + 2 * r;
            float bia0 = bo[gn], bia1 = bo[gn + 1];
            *(float2*)&out[(size_t)row0 * DD + gn] =
                make_float2(acc[mt][nt][0] + bia0, acc[mt][nt][1] + bia1);
            *(float2*)&out[(size_t)(row0 + 8) * DD + gn] =
                make_float2(acc[mt][nt][2] + bia0, acc[mt][nt][3] + bia1);
        }
    }
}

// ---------------------------------------------------------------------------
extern "C" void kernel_launch(void* const* d_in, const int* in_sizes, int n_in,
                              void* d_out, int out_size)
{
    const float* x  = (const float*)d_in[0];
    const float* Wq = (const float*)d_in[1];
    const float* bq = (const float*)d_in[2];
    const float* Wk = (const float*)d_in[3];
    const float* bk = (const float*)d_in[4];
    const float* Wv = (const float*)d_in[5];
    const float* bv = (const float*)d_in[6];
    const float* Wo = (const float*)d_in[7];
    const float* bo = (const float*)d_in[8];

    float* out  = (float*)d_out;
    float* wptr = out + (size_t)BB * SS * DD;   // weights after output

    const int gemm_smem = 2 * PSTG * (int)sizeof(uint32_t);   // 75776
    const int attn_smem = (2*UQ_SZ + 2*SCH_SZ + 2*KBUF_SZ + 2*VBUF_SZ + 32)
                          * (int)sizeof(uint32_t);            // 196736

    cudaFuncSetAttribute(proj_bf16,    cudaFuncAttributeMaxDynamicSharedMemorySize, gemm_smem);
    cudaFuncSetAttribute(outproj_bf16, cudaFuncAttributeMaxDynamicSharedMemorySize, gemm_smem);
    cudaFuncSetAttribute(attn_bf16,    cudaFuncAttributeMaxDynamicSharedMemorySize, attn_smem);

    presplit<<<512, 256>>>(x, Wq, Wk, Wv, Wo);
    proj_bf16<<<dim3(MM/128, NQKV/128), 256, gemm_smem>>>(bq, bk, bv);
    repack_qkv<<<512, 256>>>();
    attn_bf16<<<dim3(BH, SS/QROWS), 256, attn_smem>>>(wptr);
    outproj_bf16<<<dim3(MM/128, DD/128), 256, gemm_smem>>>(bo, out);
}

// round 6
// speedup vs baseline: 2.9478x; 1.0377x over previous
#include <cuda_runtime.h>
#include <cuda_bf16.h>
#include <cstdint>

#define BB 4
#define SS 1024
#define DD 1024
#define HH 16
#define DKK 64
#define DVV 32
#define BH (BB*HH)          // 64
#define MM (BB*SS)          // 4096
#define CDIM (HH*DVV)       // 512
#define NQKV (HH*160)       // 2560

// fp32 intermediates
__device__ float g_q[BH*SS*DKK];
__device__ float g_k[BH*SS*DKK];
__device__ float g_v[BH*SS*DVV];

// packed bf16x2 split operands (hi/lo)
__device__ uint32_t XH[MM*512],  XL[MM*512];
__device__ uint32_t WH[512*NQKV], WL[512*NQKV];
__device__ uint32_t WOH[256*DD],  WOL[256*DD];
__device__ uint32_t QH[BH*SS*32], QL[BH*SS*32];
__device__ uint32_t KH[BH*SS*32], KL[BH*SS*32];
__device__ uint32_t VH[BH*512*32], VL[BH*512*32];
__device__ uint32_t GCH[MM*256],  GCL[MM*256];

// ---------------------------------------------------------------------------
__device__ __forceinline__ uint32_t smem_u32(const void* p){
    return (uint32_t)__cvta_generic_to_shared(p);
}
__device__ __forceinline__ void cp16(uint32_t dst, const void* src){
    asm volatile("cp.async.cg.shared.global [%0], [%1], 16;\n" :: "r"(dst), "l"(src));
}
__device__ __forceinline__ void cp_commit(){ asm volatile("cp.async.commit_group;\n"); }
template<int N> __device__ __forceinline__ void cp_wait(){
    asm volatile("cp.async.wait_group %0;\n" :: "n"(N));
}
__device__ __forceinline__ void mma_bf16(float* d, const uint32_t* a, const uint32_t* b){
    asm volatile(
      "mma.sync.aligned.m16n8k16.row.col.f32.bf16.bf16.f32 "
      "{%0,%1,%2,%3},{%4,%5,%6,%7},{%8,%9},{%0,%1,%2,%3};\n"
      : "+f"(d[0]),"+f"(d[1]),"+f"(d[2]),"+f"(d[3])
      : "r"(a[0]),"r"(a[1]),"r"(a[2]),"r"(a[3]),"r"(b[0]),"r"(b[1]));
}
__device__ __forceinline__ uint32_t b2u(__nv_bfloat162 h){
    return *reinterpret_cast<uint32_t*>(&h);
}
__device__ __forceinline__ float2 u2f2(uint32_t u){
    __nv_bfloat162 h = *reinterpret_cast<__nv_bfloat162*>(&u);
    return __bfloat1622float2(h);
}
__device__ __forceinline__ void pack_split(float v0, float v1, uint32_t& hi, uint32_t& lo){
    __nv_bfloat162 h = __floats2bfloat162_rn(v0, v1);
    hi = b2u(h);
    float r0 = v0 - __bfloat162float(h.x);
    float r1 = v1 - __bfloat162float(h.y);
    lo = b2u(__floats2bfloat162_rn(r0, r1));
}

// ---------------------------------------------------------------------------
// K0: presplit x, fused W, Wo
// ---------------------------------------------------------------------------
__global__ void presplit(const float* __restrict__ x,
                         const float* __restrict__ Wq, const float* __restrict__ Wk,
                         const float* __restrict__ Wv, const float* __restrict__ Wo)
{
    const int nth = gridDim.x * blockDim.x;
    const int t0  = blockIdx.x * blockDim.x + threadIdx.x;
    for (int idx = t0; idx < MM*512; idx += nth) {
        int row = idx >> 9, cp = idx & 511;
        float2 v = *(const float2*)&x[(size_t)row * DD + 2*cp];
        pack_split(v.x, v.y, XH[idx], XL[idx]);
    }
    for (int idx = t0; idx < 512*NQKV; idx += nth) {
        int kp = idx / NQKV, gn = idx - kp * NQKV;
        int h = gn / 160, off = gn - h * 160;
        int d0 = 2*kp, d1 = 2*kp + 1;
        float w0, w1;
        if (off < 64) {
            w0 = Wq[((size_t)h*DD + d0)*DKK + off];
            w1 = Wq[((size_t)h*DD + d1)*DKK + off];
        } else if (off < 128) {
            w0 = Wk[((size_t)h*DD + d0)*DKK + off - 64];
            w1 = Wk[((size_t)h*DD + d1)*DKK + off - 64];
        } else {
            w0 = Wv[((size_t)h*DD + d0)*DVV + off - 128];
            w1 = Wv[((size_t)h*DD + d1)*DVV + off - 128];
        }
        pack_split(w0, w1, WH[idx], WL[idx]);
    }
    for (int idx = t0; idx < 256*DD; idx += nth) {
        int kp = idx >> 10, n = idx & 1023;
        float w0 = Wo[(size_t)(2*kp)*DD + n];
        float w1 = Wo[(size_t)(2*kp + 1)*DD + n];
        pack_split(w0, w1, WOH[idx], WOL[idx]);
    }
}

// ---------------------------------------------------------------------------
// K2: repack q/k (colpair) and v (keypair)
// ---------------------------------------------------------------------------
__global__ void repack_qkv()
{
    const int nth = gridDim.x * blockDim.x;
    const int t0  = blockIdx.x * blockDim.x + threadIdx.x;
    for (int idx = t0; idx < BH*SS*32; idx += nth) {
        int row = idx >> 5, cp = idx & 31;
        float2 vq = *(const float2*)&g_q[(size_t)row * DKK + 2*cp];
        pack_split(vq.x, vq.y, QH[idx], QL[idx]);
        float2 vk = *(const float2*)&g_k[(size_t)row * DKK + 2*cp];
        pack_split(vk.x, vk.y, KH[idx], KL[idx]);
    }
    for (int idx = t0; idx < BH*512*32; idx += nth) {
        int bh = idx >> 14, rem = idx & 16383;
        int kp = rem >> 5, dv = rem & 31;
        size_t s0 = ((size_t)bh*SS + 2*kp) * DVV + dv;
        pack_split(g_v[s0], g_v[s0 + DVV], VH[idx], VL[idx]);
    }
}

// ---------------------------------------------------------------------------
// K1: QKV projection, 3-term bf16 split, 512 threads (16 warps, tile 32x32)
// ---------------------------------------------------------------------------
#define PA_STR 20
#define PB_STR 136
#define PA_SZ (128*PA_STR)
#define PB_SZ (16*PB_STR)
#define PSTG (2*PA_SZ + 2*PB_SZ)

__global__ void __launch_bounds__(512,1) proj_bf16(
    const float* __restrict__ bq, const float* __restrict__ bk,
    const float* __restrict__ bv)
{
    extern __shared__ uint32_t sm32[];
    const int tid  = threadIdx.x;
    const int lane = tid & 31, warp = tid >> 5;
    const int wm = warp & 3, wn = warp >> 2;
    const int r = lane & 3, g = lane >> 2;
    const int m0 = blockIdx.x * 128;
    const int n0 = blockIdx.y * 128;
    uint32_t sb = smem_u32(sm32);

    float acc[2][4][4];
    #pragma unroll
    for (int mt = 0; mt < 2; mt++)
        #pragma unroll
        for (int nt = 0; nt < 4; nt++)
            #pragma unroll
            for (int i = 0; i < 4; i++) acc[mt][nt][i] = 0.f;

    auto issue_load = [&](int s, int it) {
        uint32_t base = sb + (uint32_t)(s * PSTG) * 4u;
        #pragma unroll
        for (int p = 0; p < 2; p++) {
            const uint32_t* src = p ? XL : XH;
            uint32_t dstb = base + (uint32_t)(p * PA_SZ) * 4u;
            int row = tid >> 2, c4 = (tid & 3) * 4;
            cp16(dstb + (uint32_t)(row * PA_STR + c4) * 4u,
                 &src[(size_t)(m0 + row) * 512 + it * 16 + c4]);
        }
        #pragma unroll
        for (int p = 0; p < 2; p++) {
            const uint32_t* src = p ? WL : WH;
            uint32_t dstb = base + (uint32_t)(2 * PA_SZ + p * PB_SZ) * 4u;
            int kp = tid >> 5, c = (tid & 31) * 4;
            cp16(dstb + (uint32_t)(kp * PB_STR + c) * 4u,
                 &src[(size_t)(it * 16 + kp) * NQKV + n0 + c]);
        }
    };

    issue_load(0, 0);
    cp_commit();

    for (int it = 0; it < 32; it++) {
        if (it + 1 < 32) { issue_load((it + 1) & 1, it + 1); cp_commit(); cp_wait<1>(); }
        else             { cp_wait<0>(); }
        __syncthreads();

        const uint32_t* AHs = sm32 + (it & 1) * PSTG;
        const uint32_t* ALs = AHs + PA_SZ;
        const uint32_t* BHs = AHs + 2 * PA_SZ;
        const uint32_t* BLs = BHs + PB_SZ;

        #pragma unroll
        for (int kt = 0; kt < 2; kt++) {
            uint32_t ah[2][4], al[2][4], bh2[4][2], bl2[4][2];
            #pragma unroll
            for (int mt = 0; mt < 2; mt++) {
                int row = wm * 32 + mt * 16;
                int a0 = (row + g) * PA_STR + kt * 8 + r;
                int a1 = (row + g + 8) * PA_STR + kt * 8 + r;
                ah[mt][0] = AHs[a0]; ah[mt][1] = AHs[a1];
                ah[mt][2] = AHs[a0 + 4]; ah[mt][3] = AHs[a1 + 4];
                al[mt][0] = ALs[a0]; al[mt][1] = ALs[a1];
                al[mt][2] = ALs[a0 + 4]; al[mt][3] = ALs[a1 + 4];
            }
            #pragma unroll
            for (int nt = 0; nt < 4; nt++) {
                int col = wn * 32 + nt * 8 + g;
                int b0 = (kt * 8 + r) * PB_STR + col;
                int b1 = (kt * 8 + r + 4) * PB_STR + col;
                bh2[nt][0] = BHs[b0]; bh2[nt][1] = BHs[b1];
                bl2[nt][0] = BLs[b0]; bl2[nt][1] = BLs[b1];
            }
            #pragma unroll
            for (int mt = 0; mt < 2; mt++)
                #pragma unroll
                for (int nt = 0; nt < 4; nt++) {
                    mma_bf16(acc[mt][nt], ah[mt], bh2[nt]);
                    mma_bf16(acc[mt][nt], ah[mt], bl2[nt]);
                    mma_bf16(acc[mt][nt], al[mt], bh2[nt]);
                }
        }
        __syncthreads();
    }

    #pragma unroll
    for (int mt = 0; mt < 2; mt++) {
        int row0 = m0 + wm * 32 + mt * 16 + g;
        #pragma unroll
        for (int nt = 0; nt < 4; nt++) {
            int gn = n0 + wn * 32 + nt * 8 + 2 * r;
            int h = gn / 160, off = gn - h * 160;
            float bia0, bia1;
            float *dst0, *dst1;
            int b0_ = row0 >> 10, s0_ = row0 & 1023;
            int b1_ = (row0 + 8) >> 10, s1_ = (row0 + 8) & 1023;
            size_t bhs0, bhs1;
            if (off < 64) {
                bia0 = bq[h*DKK + off]; bia1 = bq[h*DKK + off + 1];
                bhs0 = ((size_t)(b0_*HH + h))*SS + s0_;
                bhs1 = ((size_t)(b1_*HH + h))*SS + s1_;
                dst0 = g_q + bhs0*DKK + off; dst1 = g_q + bhs1*DKK + off;
            } else if (off < 128) {
                int o = off - 64;
                bia0 = bk[h*DKK + o]; bia1 = bk[h*DKK + o + 1];
                bhs0 = ((size_t)(b0_*HH + h))*SS + s0_;
                bhs1 = ((size_t)(b1_*HH + h))*SS + s1_;
                dst0 = g_k + bhs0*DKK + o; dst1 = g_k + bhs1*DKK + o;
            } else {
                int o = off - 128;
                bia0 = bv[h*DVV + o]; bia1 = bv[h*DVV + o + 1];
                bhs0 = ((size_t)(b0_*HH + h))*SS + s0_;
                bhs1 = ((size_t)(b1_*HH + h))*SS + s1_;
                dst0 = g_v + bhs0*DVV + o; dst1 = g_v + bhs1*DVV + o;
            }
            *(float2*)dst0 = make_float2(acc[mt][nt][0] + bia0, acc[mt][nt][1] + bia1);
            *(float2*)dst1 = make_float2(acc[mt][nt][2] + bia0, acc[mt][nt][3] + bia1);
        }
    }
}

// ---------------------------------------------------------------------------
// K3: attention, warp-specialized. 512 threads: warps 0-7 produce exp-scores
// (QK), warps 8-15 consume them (PV), pipelined one chunk apart; softmax-free
// overlap (PV uses unnormalized exp; normalization at epilogue via sinv).
// K/V ring buffers 3-deep -> single __syncthreads per chunk.
// ---------------------------------------------------------------------------
#define QROWS 32
#define SC2_STR 516
#define T_STR 36
#define UQ_SZ (QROWS*T_STR)          // 1152
#define SCH_SZ (QROWS*SC2_STR)       // 16512
#define KBUF_SZ (2*64*T_STR)         // hi+lo = 4608
#define VBUF_SZ (2*32*T_STR)         // hi+lo = 2304

__global__ void __launch_bounds__(512,1) attn_bf16(float* __restrict__ wout)
{
    extern __shared__ uint32_t sm32[];
    uint32_t* uqh = sm32;
    uint32_t* uql = uqh + UQ_SZ;
    uint32_t* sch = sm32 + 2*UQ_SZ;
    uint32_t* scl = sch + SCH_SZ;
    uint32_t* kbase = sm32 + 2*UQ_SZ + 2*SCH_SZ;   // 3 x KBUF_SZ
    uint32_t* vbase = kbase + 3*KBUF_SZ;           // 3 x VBUF_SZ
    float*    sinv = (float*)(vbase + 3*VBUF_SZ);

    const int bh = blockIdx.x, qt = blockIdx.y;
    const int tid = threadIdx.x;
    const int lane = tid & 31, warp = tid >> 5;
    const int r = lane & 3, g = lane >> 2;
    const bool producer = (tid < 256);
    const int ctid = tid - 256;                    // consumer-local tid
    const size_t base32 = (size_t)bh * SS + qt * QROWS;
    const size_t kbase32 = (size_t)bh * SS;

    uint32_t uqa = smem_u32(uqh), kba = smem_u32(kbase), vba = smem_u32(vbase);

    // prologue
    if (producer) {
        // Q hi/lo (one cp16 per thread per plane)
        int row = tid >> 3, c4 = (tid & 7) * 4;
        cp16(uqa + (uint32_t)(row * T_STR + c4) * 4u, &QH[(base32 + row) * 32 + c4]);
        cp16(uqa + (uint32_t)(UQ_SZ + row * T_STR + c4) * 4u, &QL[(base32 + row) * 32 + c4]);
        // K chunk 0
        #pragma unroll
        for (int p = 0; p < 2; p++) {
            const uint32_t* src = p ? KL : KH;
            #pragma unroll
            for (int i = 0; i < 2; i++) {
                int flat = tid + i * 256;
                int key = flat >> 3, kc4 = (flat & 7) * 4;
                cp16(kba + (uint32_t)(p * (KBUF_SZ/2) + key * T_STR + kc4) * 4u,
                     &src[(kbase32 + key) * 32 + kc4]);
            }
        }
        cp_commit();
    } else {
        // V chunk 0
        int kp = ctid >> 3, c4 = (ctid & 7) * 4;
        cp16(vba + (uint32_t)(kp * T_STR + c4) * 4u,
             &VH[((size_t)bh * 512 + kp) * 32 + c4]);
        cp16(vba + (uint32_t)(VBUF_SZ/2 + kp * T_STR + c4) * 4u,
             &VL[((size_t)bh * 512 + kp) * 32 + c4]);
        cp_commit();
    }

    uint32_t qah[2][4][4], qal[2][4][4];
    float phh[4] = {0,0,0,0}, phl[4] = {0,0,0,0}, plh[4] = {0,0,0,0};
    const int w2 = warp - 8;               // consumer warp id 0..7
    const int mtp = w2 & 1, ntp = w2 >> 1;

    for (int kc = 0; kc <= 16; kc++) {
        // --- prefetch + wait (per-thread cp.async groups) ---
        if (producer) {
            if (kc < 16) {
                if (kc + 1 < 16) {
                    uint32_t dstb = kba + (uint32_t)(((kc + 1) % 3) * KBUF_SZ) * 4u;
                    #pragma unroll
                    for (int p = 0; p < 2; p++) {
                        const uint32_t* src = p ? KL : KH;
                        #pragma unroll
                        for (int i = 0; i < 2; i++) {
                            int flat = tid + i * 256;
                            int key = flat >> 3, kc4 = (flat & 7) * 4;
                            cp16(dstb + (uint32_t)(p * (KBUF_SZ/2) + key * T_STR + kc4) * 4u,
                                 &src[(kbase32 + (kc + 1) * 64 + key) * 32 + kc4]);
                        }
                    }
                    cp_commit(); cp_wait<1>();
                } else cp_wait<0>();
            }
        } else {
            if (kc >= 1 && kc < 16) {
                uint32_t dstb = vba + (uint32_t)((kc % 3) * VBUF_SZ) * 4u;
                int kp = ctid >> 3, c4 = (ctid & 7) * 4;
                cp16(dstb + (uint32_t)(kp * T_STR + c4) * 4u,
                     &VH[((size_t)bh * 512 + kc * 32 + kp) * 32 + c4]);
                cp16(dstb + (uint32_t)(VBUF_SZ/2 + kp * T_STR + c4) * 4u,
                     &VL[((size_t)bh * 512 + kc * 32 + kp) * 32 + c4]);
                cp_commit();
            }
            if (kc >= 1) { if (kc < 16) cp_wait<1>(); else cp_wait<0>(); }
        }
        __syncthreads();

        // --- compute ---
        if (producer) {
            if (kc == 0) {
                #pragma unroll
                for (int mt = 0; mt < 2; mt++)
                    #pragma unroll
                    for (int kt = 0; kt < 4; kt++) {
                        int a0 = (mt*16 + g) * T_STR + kt*8 + r;
                        int a1 = (mt*16 + g + 8) * T_STR + kt*8 + r;
                        qah[mt][kt][0] = uqh[a0]; qah[mt][kt][1] = uqh[a1];
                        qah[mt][kt][2] = uqh[a0+4]; qah[mt][kt][3] = uqh[a1+4];
                        qal[mt][kt][0] = uql[a0]; qal[mt][kt][1] = uql[a1];
                        qal[mt][kt][2] = uql[a0+4]; qal[mt][kt][3] = uql[a1+4];
                    }
            }
            if (kc < 16) {
                const uint32_t* khb = kbase + (kc % 3) * KBUF_SZ;
                const uint32_t* klb = khb + KBUF_SZ/2;
                float hh[2][4], hl[2][4], lh[2][4];
                #pragma unroll
                for (int mt = 0; mt < 2; mt++)
                    #pragma unroll
                    for (int i = 0; i < 4; i++) { hh[mt][i]=0.f; hl[mt][i]=0.f; lh[mt][i]=0.f; }
                #pragma unroll
                for (int kt = 0; kt < 4; kt++) {
                    uint32_t bbh[2], bbl[2];
                    int b0 = (warp*8 + g) * T_STR + kt*8 + r;
                    bbh[0] = khb[b0]; bbh[1] = khb[b0 + 4];
                    bbl[0] = klb[b0]; bbl[1] = klb[b0 + 4];
                    mma_bf16(hh[0], qah[0][kt], bbh);
                    mma_bf16(hh[1], qah[1][kt], bbh);
                    mma_bf16(hl[0], qah[0][kt], bbl);
                    mma_bf16(hl[1], qah[1][kt], bbl);
                    mma_bf16(lh[0], qal[0][kt], bbh);
                    mma_bf16(lh[1], qal[1][kt], bbh);
                }
                int keyb2 = kc * 32 + warp * 4;
                #pragma unroll
                for (int mt = 0; mt < 2; mt++) {
                    float s0 = (hh[mt][0] + hl[mt][0] + lh[mt][0]) * 0.125f;
                    float s1 = (hh[mt][1] + hl[mt][1] + lh[mt][1]) * 0.125f;
                    float s2 = (hh[mt][2] + hl[mt][2] + lh[mt][2]) * 0.125f;
                    float s3 = (hh[mt][3] + hl[mt][3] + lh[mt][3]) * 0.125f;
                    float e0 = __expf(s0), e1 = __expf(s1), e2 = __expf(s2), e3 = __expf(s3);
                    int row = mt * 16 + g;
                    uint32_t hi, lo;
                    pack_split(e0, e1, hi, lo);
                    sch[row * SC2_STR + keyb2 + r] = hi;
                    scl[row * SC2_STR + keyb2 + r] = lo;
                    pack_split(e2, e3, hi, lo);
                    sch[(row + 8) * SC2_STR + keyb2 + r] = hi;
                    scl[(row + 8) * SC2_STR + keyb2 + r] = lo;
                }
            } else {
                // kc == 16: all scores written & visible -> row sums
                int row0 = warp * 4;
                #pragma unroll
                for (int rr = 0; rr < 4; rr++) {
                    int row = row0 + rr;
                    float s = 0.f;
                    #pragma unroll
                    for (int i = 0; i < 4; i++) {
                        uint4 h4 = *(const uint4*)(sch + row * SC2_STR + lane * 4 + i * 128);
                        uint4 l4 = *(const uint4*)(scl + row * SC2_STR + lane * 4 + i * 128);
                        float2 a0 = u2f2(h4.x), a1 = u2f2(h4.y), a2 = u2f2(h4.z), a3 = u2f2(h4.w);
                        float2 c0 = u2f2(l4.x), c1 = u2f2(l4.y), c2 = u2f2(l4.z), c3 = u2f2(l4.w);
                        s += a0.x + a0.y + a1.x + a1.y + a2.x + a2.y + a3.x + a3.y;
                        s += c0.x + c0.y + c1.x + c1.y + c2.x + c2.y + c3.x + c3.y;
                    }
                    #pragma unroll
                    for (int o = 16; o; o >>= 1) s += __shfl_xor_sync(0xffffffffu, s, o);
                    if (lane == 0) sinv[row] = 1.f / s;
                }
            }
        } else if (kc >= 1) {
            const int vc = kc - 1;
            const uint32_t* vhb = vbase + (vc % 3) * VBUF_SZ;
            const uint32_t* vlb = vhb + VBUF_SZ/2;
            const int row = mtp * 16;
            #pragma unroll
            for (int kt = 0; kt < 4; kt++) {
                int kb2 = vc * 32 + kt * 8;
                uint32_t ah[4], al[4];
                int a0 = (row + g) * SC2_STR + kb2 + r;
                int a1 = (row + g + 8) * SC2_STR + kb2 + r;
                ah[0] = sch[a0];     ah[1] = sch[a1];
                ah[2] = sch[a0 + 4]; ah[3] = sch[a1 + 4];
                al[0] = scl[a0];     al[1] = scl[a1];
                al[2] = scl[a0 + 4]; al[3] = scl[a1 + 4];
                uint32_t bbh[2], bbl[2];
                int b0 = (kt*8 + r) * T_STR + ntp*8 + g;
                int b1 = (kt*8 + r + 4) * T_STR + ntp*8 + g;
                bbh[0] = vhb[b0]; bbh[1] = vhb[b1];
                bbl[0] = vlb[b0]; bbl[1] = vlb[b1];
                mma_bf16(phh, ah, bbh);
                mma_bf16(phl, ah, bbl);
                mma_bf16(plh, al, bbh);
            }
        }
    }
    __syncthreads();   // sinv + last PV visible

    // consumer epilogue: combine, normalize, write packed concat
    if (!producer) {
        float pacc[4];
        #pragma unroll
        for (int i = 0; i < 4; i++) pacc[i] = phh[i] + phl[i] + plh[i];
        int row0 = mtp * 16 + g;
        float i0 = sinv[row0], i1 = sinv[row0 + 8];
        int b_ = bh >> 4, h = bh & 15;
        int cp = h * 16 + ntp * 4 + r;
        size_t r0 = (size_t)(b_ * SS + qt * QROWS + row0);
        uint32_t hi, lo;
        pack_split(pacc[0] * i0, pacc[1] * i0, hi, lo);
        GCH[r0 * 256 + cp] = hi; GCL[r0 * 256 + cp] = lo;
        pack_split(pacc[2] * i1, pacc[3] * i1, hi, lo);
        GCH[(r0 + 8) * 256 + cp] = hi; GCL[(r0 + 8) * 256 + cp] = lo;
    }

    // all 512 threads: stream normalized weights
    #pragma unroll 4
    for (int i = 0; i < 16; i++) {
        int f = tid + i * 512;
        int row = f >> 8, cpp = (f & 255) * 2;
        uint2 h2 = *(const uint2*)(sch + row * SC2_STR + cpp);
        uint2 l2 = *(const uint2*)(scl + row * SC2_STR + cpp);
        float iv = sinv[row];
        float2 w0 = u2f2(h2.x), w1 = u2f2(h2.y);
        float2 d0 = u2f2(l2.x), d1 = u2f2(l2.y);
        float4 v;
        v.x = (w0.x + d0.x) * iv;
        v.y = (w0.y + d0.y) * iv;
        v.z = (w1.x + d1.x) * iv;
        v.w = (w1.y + d1.y) * iv;
        *(float4*)(wout + ((kbase32 + qt * QROWS + row) << 10) + cpp * 2) = v;
    }
}

// ---------------------------------------------------------------------------
// K4: output projection, 3-term bf16 split, 512 threads. grid (32, 8)
// ---------------------------------------------------------------------------
__global__ void __launch_bounds__(512,1) outproj_bf16(
    const float* __restrict__ bo, float* __restrict__ out)
{
    extern __shared__ uint32_t sm32[];
    const int tid  = threadIdx.x;
    const int lane = tid & 31, warp = tid >> 5;
    const int wm = warp & 3, wn = warp >> 2;
    const int r = lane & 3, g = lane >> 2;
    const int m0 = blockIdx.x * 128;
    const int n0 = blockIdx.y * 128;
    uint32_t sb = smem_u32(sm32);

    float acc[2][4][4];
    #pragma unroll
    for (int mt = 0; mt < 2; mt++)
        #pragma unroll
        for (int nt = 0; nt < 4; nt++)
            #pragma unroll
            for (int i = 0; i < 4; i++) acc[mt][nt][i] = 0.f;

    auto issue_load = [&](int s, int it) {
        uint32_t base = sb + (uint32_t)(s * PSTG) * 4u;
        #pragma unroll
        for (int p = 0; p < 2; p++) {
            const uint32_t* src = p ? GCL : GCH;
            uint32_t dstb = base + (uint32_t)(p * PA_SZ) * 4u;
            int row = tid >> 2, c4 = (tid & 3) * 4;
            cp16(dstb + (uint32_t)(row * PA_STR + c4) * 4u,
                 &src[(size_t)(m0 + row) * 256 + it * 16 + c4]);
        }
        #pragma unroll
        for (int p = 0; p < 2; p++) {
            const uint32_t* src = p ? WOL : WOH;
            uint32_t dstb = base + (uint32_t)(2 * PA_SZ + p * PB_SZ) * 4u;
            int kp = tid >> 5, c = (tid & 31) * 4;
            cp16(dstb + (uint32_t)(kp * PB_STR + c) * 4u,
                 &src[(size_t)(it * 16 + kp) * DD + n0 + c]);
        }
    };

    issue_load(0, 0);
    cp_commit();

    for (int it = 0; it < 16; it++) {
        if (it + 1 < 16) { issue_load((it + 1) & 1, it + 1); cp_commit(); cp_wait<1>(); }
        else             { cp_wait<0>(); }
        __syncthreads();

        const uint32_t* AHs = sm32 + (it & 1) * PSTG;
        const uint32_t* ALs = AHs + PA_SZ;
        const uint32_t* BHs = AHs + 2 * PA_SZ;
        const uint32_t* BLs = BHs + PB_SZ;

        #pragma unroll
        for (int kt = 0; kt < 2; kt++) {
            uint32_t ah[2][4], al[2][4], bh2[4][2], bl2[4][2];
            #pragma unroll
            for (int mt = 0; mt < 2; mt++) {
                int row = wm * 32 + mt * 16;
                int a0 = (row + g) * PA_STR + kt * 8 + r;
                int a1 = (row + g + 8) * PA_STR + kt * 8 + r;
                ah[mt][0] = AHs[a0]; ah[mt][1] = AHs[a1];
                ah[mt][2] = AHs[a0 + 4]; ah[mt][3] = AHs[a1 + 4];
                al[mt][0] = ALs[a0]; al[mt][1] = ALs[a1];
                al[mt][2] = ALs[a0 + 4]; al[mt][3] = ALs[a1 + 4];
            }
            #pragma unroll
            for (int nt = 0; nt < 4; nt++) {
                int col = wn * 32 + nt * 8 + g;
                int b0 = (kt * 8 + r) * PB_STR + col;
                int b1 = (kt * 8 + r + 4) * PB_STR + col;
                bh2[nt][0] = BHs[b0]; bh2[nt][1] = BHs[b1];
                bl2[nt][0] = BLs[b0]; bl2[nt][1] = BLs[b1];
            }
            #pragma unroll
            for (int mt = 0; mt < 2; mt++)
                #pragma unroll
                for (int nt = 0; nt < 4; nt++) {
                    mma_bf16(acc[mt][nt], ah[mt], bh2[nt]);
                    mma_bf16(acc[mt][nt], ah[mt], bl2[nt]);
                    mma_bf16(acc[mt][nt], al[mt], bh2[nt]);
                }
        }
        __syncthreads();
    }

    #pragma unroll
    for (int mt = 0; mt < 2; mt++) {
        int row0 = m0 + wm * 32 + mt * 16 + g;
        #pragma unroll
        for (int nt = 0; nt < 4; nt++) {
            int gn = n0 + wn * 32 + nt * 8 + 2 * r;
            float bia0 = bo[gn], bia1 = bo[gn + 1];
            *(float2*)&out[(size_t)row0 * DD + gn] =
                make_float2(acc[mt][nt][0] + bia0, acc[mt][nt][1] + bia1);
            *(float2*)&out[(size_t)(row0 + 8) * DD + gn] =
                make_float2(acc[mt][nt][2] + bia0, acc[mt][nt][3] + bia1);
        }
    }
}

// ---------------------------------------------------------------------------
extern "C" void kernel_launch(void* const* d_in, const int* in_sizes, int n_in,
                              void* d_out, int out_size)
{
    const float* x  = (const float*)d_in[0];
    const float* Wq = (const float*)d_in[1];
    const float* bq = (const float*)d_in[2];
    const float* Wk = (const float*)d_in[3];
    const float* bk = (const float*)d_in[4];
    const float* Wv = (const float*)d_in[5];
    const float* bv = (const float*)d_in[6];
    const float* Wo = (const float*)d_in[7];
    const float* bo = (const float*)d_in[8];

    float* out  = (float*)d_out;
    float* wptr = out + (size_t)BB * SS * DD;

    const int gemm_smem = 2 * PSTG * (int)sizeof(uint32_t);   // 75776
    const int attn_smem = (2*UQ_SZ + 2*SCH_SZ + 3*KBUF_SZ + 3*VBUF_SZ + 32)
                          * (int)sizeof(uint32_t);            // 224384

    cudaFuncSetAttribute(proj_bf16,    cudaFuncAttributeMaxDynamicSharedMemorySize, gemm_smem);
    cudaFuncSetAttribute(outproj_bf16, cudaFuncAttributeMaxDynamicSharedMemorySize, gemm_smem);
    cudaFuncSetAttribute(attn_bf16,    cudaFuncAttributeMaxDynamicSharedMemorySize, attn_smem);

    presplit<<<512, 256>>>(x, Wq, Wk, Wv, Wo);
    proj_bf16<<<dim3(MM/128, NQKV/128), 512, gemm_smem>>>(bq, bk, bv);
    repack_qkv<<<512, 256>>>();
    attn_bf16<<<dim3(BH, SS/QROWS), 512, attn_smem>>>(wptr);
    outproj_bf16<<<dim3(MM/128, DD/128), 512, gemm_smem>>>(bo, out);
}

// round 7
// speedup vs baseline: 3.0976x; 1.0508x over previous
#include <cuda_runtime.h>
#include <cuda_bf16.h>
#include <cstdint>

#define BB 4
#define SS 1024
#define DD 1024
#define HH 16
#define DKK 64
#define DVV 32
#define BH (BB*HH)          // 64
#define MM (BB*SS)          // 4096
#define CDIM (HH*DVV)       // 512
#define NQKV (HH*160)       // 2560

// packed bf16x2 split operands (hi/lo)
__device__ uint32_t XH[MM*512],  XL[MM*512];       // x colpair-packed
__device__ uint32_t WH[512*NQKV], WL[512*NQKV];    // fused W kpair-packed
__device__ uint32_t WOH[256*DD],  WOL[256*DD];     // Wo kpair-packed
__device__ uint32_t QH[BH*SS*32], QL[BH*SS*32];    // q colpair-packed
__device__ uint32_t KH[BH*SS*32], KL[BH*SS*32];    // k colpair-packed
__device__ uint32_t VH[BH*512*32], VL[BH*512*32];  // v keypair-packed
__device__ uint32_t GCH[MM*256],  GCL[MM*256];     // concat colpair-packed

// ---------------------------------------------------------------------------
__device__ __forceinline__ uint32_t smem_u32(const void* p){
    return (uint32_t)__cvta_generic_to_shared(p);
}
__device__ __forceinline__ void cp16(uint32_t dst, const void* src){
    asm volatile("cp.async.cg.shared.global [%0], [%1], 16;\n" :: "r"(dst), "l"(src));
}
__device__ __forceinline__ void cp_commit(){ asm volatile("cp.async.commit_group;\n"); }
template<int N> __device__ __forceinline__ void cp_wait(){
    asm volatile("cp.async.wait_group %0;\n" :: "n"(N));
}
__device__ __forceinline__ void mma_bf16(float* d, const uint32_t* a, const uint32_t* b){
    asm volatile(
      "mma.sync.aligned.m16n8k16.row.col.f32.bf16.bf16.f32 "
      "{%0,%1,%2,%3},{%4,%5,%6,%7},{%8,%9},{%0,%1,%2,%3};\n"
      : "+f"(d[0]),"+f"(d[1]),"+f"(d[2]),"+f"(d[3])
      : "r"(a[0]),"r"(a[1]),"r"(a[2]),"r"(a[3]),"r"(b[0]),"r"(b[1]));
}
__device__ __forceinline__ uint32_t b2u(__nv_bfloat162 h){
    return *reinterpret_cast<uint32_t*>(&h);
}
__device__ __forceinline__ float2 u2f2(uint32_t u){
    __nv_bfloat162 h = *reinterpret_cast<__nv_bfloat162*>(&u);
    return __bfloat1622float2(h);
}
__device__ __forceinline__ void pack_split(float v0, float v1, uint32_t& hi, uint32_t& lo){
    __nv_bfloat162 h = __floats2bfloat162_rn(v0, v1);
    hi = b2u(h);
    float r0 = v0 - __bfloat162float(h.x);
    float r1 = v1 - __bfloat162float(h.y);
    lo = b2u(__floats2bfloat162_rn(r0, r1));
}

// ---------------------------------------------------------------------------
// K0: presplit x, fused W, Wo
// ---------------------------------------------------------------------------
__global__ void presplit(const float* __restrict__ x,
                         const float* __restrict__ Wq, const float* __restrict__ Wk,
                         const float* __restrict__ Wv, const float* __restrict__ Wo)
{
    const int nth = gridDim.x * blockDim.x;
    const int t0  = blockIdx.x * blockDim.x + threadIdx.x;
    for (int idx = t0; idx < MM*512; idx += nth) {
        int row = idx >> 9, cp = idx & 511;
        float2 v = *(const float2*)&x[(size_t)row * DD + 2*cp];
        pack_split(v.x, v.y, XH[idx], XL[idx]);
    }
    for (int idx = t0; idx < 512*NQKV; idx += nth) {
        int kp = idx / NQKV, gn = idx - kp * NQKV;
        int h = gn / 160, off = gn - h * 160;
        int d0 = 2*kp, d1 = 2*kp + 1;
        float w0, w1;
        if (off < 64) {
            w0 = Wq[((size_t)h*DD + d0)*DKK + off];
            w1 = Wq[((size_t)h*DD + d1)*DKK + off];
        } else if (off < 128) {
            w0 = Wk[((size_t)h*DD + d0)*DKK + off - 64];
            w1 = Wk[((size_t)h*DD + d1)*DKK + off - 64];
        } else {
            w0 = Wv[((size_t)h*DD + d0)*DVV + off - 128];
            w1 = Wv[((size_t)h*DD + d1)*DVV + off - 128];
        }
        pack_split(w0, w1, WH[idx], WL[idx]);
    }
    for (int idx = t0; idx < 256*DD; idx += nth) {
        int kp = idx >> 10, n = idx & 1023;
        float w0 = Wo[(size_t)(2*kp)*DD + n];
        float w1 = Wo[(size_t)(2*kp + 1)*DD + n];
        pack_split(w0, w1, WOH[idx], WOL[idx]);
    }
}

// ---------------------------------------------------------------------------
// K1: QKV projection, 3-term bf16 split, 512 threads, 3-stage pipeline.
// Epilogue writes packed QH/QL, KH/KL, VH/VL DIRECTLY (repack fused).
// ---------------------------------------------------------------------------
#define PA_STR 20
#define PB_STR 136
#define PA_SZ (128*PA_STR)
#define PB_SZ (16*PB_STR)
#define PSTG (2*PA_SZ + 2*PB_SZ)   // 9472 u32 per stage

__global__ void __launch_bounds__(512,1) proj_bf16(
    const float* __restrict__ bq, const float* __restrict__ bk,
    const float* __restrict__ bv)
{
    extern __shared__ uint32_t sm32[];
    const int tid  = threadIdx.x;
    const int lane = tid & 31, warp = tid >> 5;
    const int wm = warp & 3, wn = warp >> 2;
    const int r = lane & 3, g = lane >> 2;
    const int m0 = blockIdx.x * 128;
    const int n0 = blockIdx.y * 128;
    uint32_t sb = smem_u32(sm32);

    float acc[2][4][4];
    #pragma unroll
    for (int mt = 0; mt < 2; mt++)
        #pragma unroll
        for (int nt = 0; nt < 4; nt++)
            #pragma unroll
            for (int i = 0; i < 4; i++) acc[mt][nt][i] = 0.f;

    auto issue_load = [&](int s, int it) {
        uint32_t base = sb + (uint32_t)(s * PSTG) * 4u;
        #pragma unroll
        for (int p = 0; p < 2; p++) {
            const uint32_t* src = p ? XL : XH;
            uint32_t dstb = base + (uint32_t)(p * PA_SZ) * 4u;
            int row = tid >> 2, c4 = (tid & 3) * 4;
            cp16(dstb + (uint32_t)(row * PA_STR + c4) * 4u,
                 &src[(size_t)(m0 + row) * 512 + it * 16 + c4]);
        }
        #pragma unroll
        for (int p = 0; p < 2; p++) {
            const uint32_t* src = p ? WL : WH;
            uint32_t dstb = base + (uint32_t)(2 * PA_SZ + p * PB_SZ) * 4u;
            int kp = tid >> 5, c = (tid & 31) * 4;
            cp16(dstb + (uint32_t)(kp * PB_STR + c) * 4u,
                 &src[(size_t)(it * 16 + kp) * NQKV + n0 + c]);
        }
    };

    issue_load(0, 0); cp_commit();
    issue_load(1, 1); cp_commit();

    for (int it = 0; it < 32; it++) {
        if (it + 1 < 32) cp_wait<1>(); else cp_wait<0>();
        __syncthreads();
        if (it + 2 < 32) { issue_load((it + 2) % 3, it + 2); cp_commit(); }

        const uint32_t* AHs = sm32 + (it % 3) * PSTG;
        const uint32_t* ALs = AHs + PA_SZ;
        const uint32_t* BHs = AHs + 2 * PA_SZ;
        const uint32_t* BLs = BHs + PB_SZ;

        #pragma unroll
        for (int kt = 0; kt < 2; kt++) {
            uint32_t ah[2][4], al[2][4], bh2[4][2], bl2[4][2];
            #pragma unroll
            for (int mt = 0; mt < 2; mt++) {
                int row = wm * 32 + mt * 16;
                int a0 = (row + g) * PA_STR + kt * 8 + r;
                int a1 = (row + g + 8) * PA_STR + kt * 8 + r;
                ah[mt][0] = AHs[a0]; ah[mt][1] = AHs[a1];
                ah[mt][2] = AHs[a0 + 4]; ah[mt][3] = AHs[a1 + 4];
                al[mt][0] = ALs[a0]; al[mt][1] = ALs[a1];
                al[mt][2] = ALs[a0 + 4]; al[mt][3] = ALs[a1 + 4];
            }
            #pragma unroll
            for (int nt = 0; nt < 4; nt++) {
                int col = wn * 32 + nt * 8 + g;
                int b0 = (kt * 8 + r) * PB_STR + col;
                int b1 = (kt * 8 + r + 4) * PB_STR + col;
                bh2[nt][0] = BHs[b0]; bh2[nt][1] = BHs[b1];
                bl2[nt][0] = BLs[b0]; bl2[nt][1] = BLs[b1];
            }
            #pragma unroll
            for (int mt = 0; mt < 2; mt++)
                #pragma unroll
                for (int nt = 0; nt < 4; nt++) {
                    mma_bf16(acc[mt][nt], ah[mt], bh2[nt]);
                    mma_bf16(acc[mt][nt], ah[mt], bl2[nt]);
                    mma_bf16(acc[mt][nt], al[mt], bh2[nt]);
                }
        }
    }

    // fused epilogue: split+pack directly to QH/QL, KH/KL, VH/VL
    #pragma unroll
    for (int mt = 0; mt < 2; mt++) {
        int row0 = m0 + wm * 32 + mt * 16 + g;
        int b0_ = row0 >> 10, s0_ = row0 & 1023;       // +8 never crosses batch
        #pragma unroll
        for (int nt = 0; nt < 4; nt++) {
            int gn = n0 + wn * 32 + nt * 8 + 2 * r;
            int h = gn / 160, off = gn - h * 160;       // warp-uniform region
            uint32_t hi, lo;
            if (off < 128) {
                const float* bias = (off < 64) ? bq : bk;
                int o = (off < 64) ? off : off - 64;
                uint32_t* DH = (off < 64) ? QH : KH;
                uint32_t* DL = (off < 64) ? QL : KL;
                float bia0 = bias[h*DKK + o], bia1 = bias[h*DKK + o + 1];
                size_t bhs0 = ((size_t)(b0_*HH + h))*SS + s0_;
                int cp = o >> 1;
                pack_split(acc[mt][nt][0] + bia0, acc[mt][nt][1] + bia1, hi, lo);
                DH[bhs0*32 + cp] = hi; DL[bhs0*32 + cp] = lo;
                pack_split(acc[mt][nt][2] + bia0, acc[mt][nt][3] + bia1, hi, lo);
                DH[(bhs0 + 8)*32 + cp] = hi; DL[(bhs0 + 8)*32 + cp] = lo;
            } else {
                int dv = off - 128;
                float bia0 = bv[h*DVV + dv], bia1 = bv[h*DVV + dv + 1];
                float v0 = acc[mt][nt][0] + bia0, v1 = acc[mt][nt][1] + bia1;
                float v2 = acc[mt][nt][2] + bia0, v3 = acc[mt][nt][3] + bia1;
                float p0 = __shfl_xor_sync(0xffffffffu, v0, 4);
                float p1 = __shfl_xor_sync(0xffffffffu, v1, 4);
                float p2 = __shfl_xor_sync(0xffffffffu, v2, 4);
                float p3 = __shfl_xor_sync(0xffffffffu, v3, 4);
                if ((g & 1) == 0) {      // even-g lane owns rows (s, s+1)
                    size_t vb = (size_t)(b0_*HH + h) * 512;
                    int kp = s0_ >> 1;
                    pack_split(v0, p0, hi, lo);
                    VH[(vb + kp)*32 + dv] = hi;     VL[(vb + kp)*32 + dv] = lo;
                    pack_split(v1, p1, hi, lo);
                    VH[(vb + kp)*32 + dv + 1] = hi; VL[(vb + kp)*32 + dv + 1] = lo;
                    pack_split(v2, p2, hi, lo);
                    VH[(vb + kp + 4)*32 + dv] = hi; VL[(vb + kp + 4)*32 + dv] = lo;
                    pack_split(v3, p3, hi, lo);
                    VH[(vb + kp + 4)*32 + dv + 1] = hi; VL[(vb + kp + 4)*32 + dv + 1] = lo;
                }
            }
        }
    }
}

// ---------------------------------------------------------------------------
// K3: attention, warp-specialized (512 thr), incremental row sums.
// ---------------------------------------------------------------------------
#define QROWS 32
#define SC2_STR 516
#define T_STR 36
#define UQ_SZ (QROWS*T_STR)
#define SCH_SZ (QROWS*SC2_STR)
#define KBUF_SZ (2*64*T_STR)
#define VBUF_SZ (2*32*T_STR)

__global__ void __launch_bounds__(512,1) attn_bf16(float* __restrict__ wout)
{
    extern __shared__ uint32_t sm32[];
    uint32_t* uqh = sm32;
    uint32_t* uql = uqh + UQ_SZ;
    uint32_t* sch = sm32 + 2*UQ_SZ;
    uint32_t* scl = sch + SCH_SZ;
    uint32_t* kbase = sm32 + 2*UQ_SZ + 2*SCH_SZ;
    uint32_t* vbase = kbase + 3*KBUF_SZ;
    float*    sinv = (float*)(vbase + 3*VBUF_SZ);    // 32
    float*    part = sinv + 32;                      // 8 x 32

    const int bh = blockIdx.x, qt = blockIdx.y;
    const int tid = threadIdx.x;
    const int lane = tid & 31, warp = tid >> 5;
    const int r = lane & 3, g = lane >> 2;
    const bool producer = (tid < 256);
    const int ctid = tid - 256;
    const size_t base32 = (size_t)bh * SS + qt * QROWS;
    const size_t kbase32 = (size_t)bh * SS;

    uint32_t uqa = smem_u32(uqh), kba = smem_u32(kbase), vba = smem_u32(vbase);

    if (producer) {
        int row = tid >> 3, c4 = (tid & 7) * 4;
        cp16(uqa + (uint32_t)(row * T_STR + c4) * 4u, &QH[(base32 + row) * 32 + c4]);
        cp16(uqa + (uint32_t)(UQ_SZ + row * T_STR + c4) * 4u, &QL[(base32 + row) * 32 + c4]);
        #pragma unroll
        for (int p = 0; p < 2; p++) {
            const uint32_t* src = p ? KL : KH;
            #pragma unroll
            for (int i = 0; i < 2; i++) {
                int flat = tid + i * 256;
                int key = flat >> 3, kc4 = (flat & 7) * 4;
                cp16(kba + (uint32_t)(p * (KBUF_SZ/2) + key * T_STR + kc4) * 4u,
                     &src[(kbase32 + key) * 32 + kc4]);
            }
        }
        cp_commit();
    } else {
        int kp = ctid >> 3, c4 = (ctid & 7) * 4;
        cp16(vba + (uint32_t)(kp * T_STR + c4) * 4u,
             &VH[((size_t)bh * 512 + kp) * 32 + c4]);
        cp16(vba + (uint32_t)(VBUF_SZ/2 + kp * T_STR + c4) * 4u,
             &VL[((size_t)bh * 512 + kp) * 32 + c4]);
        cp_commit();
    }

    uint32_t qah[2][4][4], qal[2][4][4];
    float phh[4] = {0,0,0,0}, phl[4] = {0,0,0,0}, plh[4] = {0,0,0,0};
    float psum[2][2] = {{0.f,0.f},{0.f,0.f}};        // producer partial row sums
    const int w2 = warp - 8;
    const int mtp = w2 & 1, ntp = w2 >> 1;

    for (int kc = 0; kc <= 16; kc++) {
        if (producer) {
            if (kc < 16) {
                if (kc + 1 < 16) {
                    uint32_t dstb = kba + (uint32_t)(((kc + 1) % 3) * KBUF_SZ) * 4u;
                    #pragma unroll
                    for (int p = 0; p < 2; p++) {
                        const uint32_t* src = p ? KL : KH;
                        #pragma unroll
                        for (int i = 0; i < 2; i++) {
                            int flat = tid + i * 256;
                            int key = flat >> 3, kc4 = (flat & 7) * 4;
                            cp16(dstb + (uint32_t)(p * (KBUF_SZ/2) + key * T_STR + kc4) * 4u,
                                 &src[(kbase32 + (kc + 1) * 64 + key) * 32 + kc4]);
                        }
                    }
                    cp_commit(); cp_wait<1>();
                } else cp_wait<0>();
            }
        } else {
            if (kc >= 1 && kc < 16) {
                uint32_t dstb = vba + (uint32_t)((kc % 3) * VBUF_SZ) * 4u;
                int kp = ctid >> 3, c4 = (ctid & 7) * 4;
                cp16(dstb + (uint32_t)(kp * T_STR + c4) * 4u,
                     &VH[((size_t)bh * 512 + kc * 32 + kp) * 32 + c4]);
                cp16(dstb + (uint32_t)(VBUF_SZ/2 + kp * T_STR + c4) * 4u,
                     &VL[((size_t)bh * 512 + kc * 32 + kp) * 32 + c4]);
                cp_commit();
            }
            if (kc >= 1) { if (kc < 16) cp_wait<1>(); else cp_wait<0>(); }
        }
        __syncthreads();

        if (producer) {
            if (kc == 0) {
                #pragma unroll
                for (int mt = 0; mt < 2; mt++)
                    #pragma unroll
                    for (int kt = 0; kt < 4; kt++) {
                        int a0 = (mt*16 + g) * T_STR + kt*8 + r;
                        int a1 = (mt*16 + g + 8) * T_STR + kt*8 + r;
                        qah[mt][kt][0] = uqh[a0]; qah[mt][kt][1] = uqh[a1];
                        qah[mt][kt][2] = uqh[a0+4]; qah[mt][kt][3] = uqh[a1+4];
                        qal[mt][kt][0] = uql[a0]; qal[mt][kt][1] = uql[a1];
                        qal[mt][kt][2] = uql[a0+4]; qal[mt][kt][3] = uql[a1+4];
                    }
            }
            if (kc < 16) {
                const uint32_t* khb = kbase + (kc % 3) * KBUF_SZ;
                const uint32_t* klb = khb + KBUF_SZ/2;
                float hh[2][4], hl[2][4], lh[2][4];
                #pragma unroll
                for (int mt = 0; mt < 2; mt++)
                    #pragma unroll
                    for (int i = 0; i < 4; i++) { hh[mt][i]=0.f; hl[mt][i]=0.f; lh[mt][i]=0.f; }
                #pragma unroll
                for (int kt = 0; kt < 4; kt++) {
                    uint32_t bbh[2], bbl[2];
                    int b0 = (warp*8 + g) * T_STR + kt*8 + r;
                    bbh[0] = khb[b0]; bbh[1] = khb[b0 + 4];
                    bbl[0] = klb[b0]; bbl[1] = klb[b0 + 4];
                    mma_bf16(hh[0], qah[0][kt], bbh);
                    mma_bf16(hh[1], qah[1][kt], bbh);
                    mma_bf16(hl[0], qah[0][kt], bbl);
                    mma_bf16(hl[1], qah[1][kt], bbl);
                    mma_bf16(lh[0], qal[0][kt], bbh);
                    mma_bf16(lh[1], qal[1][kt], bbh);
                }
                int keyb2 = kc * 32 + warp * 4;
                #pragma unroll
                for (int mt = 0; mt < 2; mt++) {
                    float s0 = (hh[mt][0] + hl[mt][0] + lh[mt][0]) * 0.125f;
                    float s1 = (hh[mt][1] + hl[mt][1] + lh[mt][1]) * 0.125f;
                    float s2 = (hh[mt][2] + hl[mt][2] + lh[mt][2]) * 0.125f;
                    float s3 = (hh[mt][3] + hl[mt][3] + lh[mt][3]) * 0.125f;
                    float e0 = __expf(s0), e1 = __expf(s1), e2 = __expf(s2), e3 = __expf(s3);
                    psum[mt][0] += e0 + e1;
                    psum[mt][1] += e2 + e3;
                    int row = mt * 16 + g;
                    uint32_t hi, lo;
                    pack_split(e0, e1, hi, lo);
                    sch[row * SC2_STR + keyb2 + r] = hi;
                    scl[row * SC2_STR + keyb2 + r] = lo;
                    pack_split(e2, e3, hi, lo);
                    sch[(row + 8) * SC2_STR + keyb2 + r] = hi;
                    scl[(row + 8) * SC2_STR + keyb2 + r] = lo;
                }
            } else {
                // kc == 16: fold partial sums (2 shfls over r) -> part[warp][row]
                #pragma unroll
                for (int mt = 0; mt < 2; mt++)
                    #pragma unroll
                    for (int j = 0; j < 2; j++) {
                        float s = psum[mt][j];
                        s += __shfl_xor_sync(0xffffffffu, s, 1);
                        s += __shfl_xor_sync(0xffffffffu, s, 2);
                        if (r == 0) part[warp * 32 + mt*16 + j*8 + g] = s;
                    }
            }
        } else if (kc >= 1) {
            const int vc = kc - 1;
            const uint32_t* vhb = vbase + (vc % 3) * VBUF_SZ;
            const uint32_t* vlb = vhb + VBUF_SZ/2;
            const int row = mtp * 16;
            #pragma unroll
            for (int kt = 0; kt < 4; kt++) {
                int kb2 = vc * 32 + kt * 8;
                uint32_t ah[4], al[4];
                int a0 = (row + g) * SC2_STR + kb2 + r;
                int a1 = (row + g + 8) * SC2_STR + kb2 + r;
                ah[0] = sch[a0];     ah[1] = sch[a1];
                ah[2] = sch[a0 + 4]; ah[3] = sch[a1 + 4];
                al[0] = scl[a0];     al[1] = scl[a1];
                al[2] = scl[a0 + 4]; al[3] = scl[a1 + 4];
                uint32_t bbh[2], bbl[2];
                int b0 = (kt*8 + r) * T_STR + ntp*8 + g;
                int b1 = (kt*8 + r + 4) * T_STR + ntp*8 + g;
                bbh[0] = vhb[b0]; bbh[1] = vhb[b1];
                bbl[0] = vlb[b0]; bbl[1] = vlb[b1];
                mma_bf16(phh, ah, bbh);
                mma_bf16(phl, ah, bbl);
                mma_bf16(plh, al, bbh);
            }
        }
    }
    __syncthreads();

    // warp 0: final row sums -> sinv
    if (tid < 32) {
        float s = 0.f;
        #pragma unroll
        for (int w = 0; w < 8; w++) s += part[w * 32 + tid];
        sinv[tid] = 1.f / s;
    }
    __syncthreads();

    // consumer epilogue: combine, normalize, write packed concat
    if (!producer) {
        float pacc[4];
        #pragma unroll
        for (int i = 0; i < 4; i++) pacc[i] = phh[i] + phl[i] + plh[i];
        int row0 = mtp * 16 + g;
        float i0 = sinv[row0], i1 = sinv[row0 + 8];
        int b_ = bh >> 4, h = bh & 15;
        int cp = h * 16 + ntp * 4 + r;
        size_t r0 = (size_t)(b_ * SS + qt * QROWS + row0);
        uint32_t hi, lo;
        pack_split(pacc[0] * i0, pacc[1] * i0, hi, lo);
        GCH[r0 * 256 + cp] = hi; GCL[r0 * 256 + cp] = lo;
        pack_split(pacc[2] * i1, pacc[3] * i1, hi, lo);
        GCH[(r0 + 8) * 256 + cp] = hi; GCL[(r0 + 8) * 256 + cp] = lo;
    }

    // all 512 threads: stream normalized weights
    #pragma unroll 4
    for (int i = 0; i < 16; i++) {
        int f = tid + i * 512;
        int row = f >> 8, cpp = (f & 255) * 2;
        uint2 h2 = *(const uint2*)(sch + row * SC2_STR + cpp);
        uint2 l2 = *(const uint2*)(scl + row * SC2_STR + cpp);
        float iv = sinv[row];
        float2 w0 = u2f2(h2.x), w1 = u2f2(h2.y);
        float2 d0 = u2f2(l2.x), d1 = u2f2(l2.y);
        float4 v;
        v.x = (w0.x + d0.x) * iv;
        v.y = (w0.y + d0.y) * iv;
        v.z = (w1.x + d1.x) * iv;
        v.w = (w1.y + d1.y) * iv;
        *(float4*)(wout + ((kbase32 + qt * QROWS + row) << 10) + cpp * 2) = v;
    }
}

// ---------------------------------------------------------------------------
// K4: output projection, 3-term bf16 split, 512 threads, 3-stage pipeline.
// ---------------------------------------------------------------------------
__global__ void __launch_bounds__(512,1) outproj_bf16(
    const float* __restrict__ bo, float* __restrict__ out)
{
    extern __shared__ uint32_t sm32[];
    const int tid  = threadIdx.x;
    const int lane = tid & 31, warp = tid >> 5;
    const int wm = warp & 3, wn = warp >> 2;
    const int r = lane & 3, g = lane >> 2;
    const int m0 = blockIdx.x * 128;
    const int n0 = blockIdx.y * 128;
    uint32_t sb = smem_u32(sm32);

    float acc[2][4][4];
    #pragma unroll
    for (int mt = 0; mt < 2; mt++)
        #pragma unroll
        for (int nt = 0; nt < 4; nt++)
            #pragma unroll
            for (int i = 0; i < 4; i++) acc[mt][nt][i] = 0.f;

    auto issue_load = [&](int s, int it) {
        uint32_t base = sb + (uint32_t)(s * PSTG) * 4u;
        #pragma unroll
        for (int p = 0; p < 2; p++) {
            const uint32_t* src = p ? GCL : GCH;
            uint32_t dstb = base + (uint32_t)(p * PA_SZ) * 4u;
            int row = tid >> 2, c4 = (tid & 3) * 4;
            cp16(dstb + (uint32_t)(row * PA_STR + c4) * 4u,
                 &src[(size_t)(m0 + row) * 256 + it * 16 + c4]);
        }
        #pragma unroll
        for (int p = 0; p < 2; p++) {
            const uint32_t* src = p ? WOL : WOH;
            uint32_t dstb = base + (uint32_t)(2 * PA_SZ + p * PB_SZ) * 4u;
            int kp = tid >> 5, c = (tid & 31) * 4;
            cp16(dstb + (uint32_t)(kp * PB_STR + c) * 4u,
                 &src[(size_t)(it * 16 + kp) * DD + n0 + c]);
        }
    };

    issue_load(0, 0); cp_commit();
    issue_load(1, 1); cp_commit();

    for (int it = 0; it < 16; it++) {
        if (it + 1 < 16) cp_wait<1>(); else cp_wait<0>();
        __syncthreads();
        if (it + 2 < 16) { issue_load((it + 2) % 3, it + 2); cp_commit(); }

        const uint32_t* AHs = sm32 + (it % 3) * PSTG;
        const uint32_t* ALs = AHs + PA_SZ;
        const uint32_t* BHs = AHs + 2 * PA_SZ;
        const uint32_t* BLs = BHs + PB_SZ;

        #pragma unroll
        for (int kt = 0; kt < 2; kt++) {
            uint32_t ah[2][4], al[2][4], bh2[4][2], bl2[4][2];
            #pragma unroll
            for (int mt = 0; mt < 2; mt++) {
                int row = wm * 32 + mt * 16;
                int a0 = (row + g) * PA_STR + kt * 8 + r;
                int a1 = (row + g + 8) * PA_STR + kt * 8 + r;
                ah[mt][0] = AHs[a0]; ah[mt][1] = AHs[a1];
                ah[mt][2] = AHs[a0 + 4]; ah[mt][3] = AHs[a1 + 4];
                al[mt][0] = ALs[a0]; al[mt][1] = ALs[a1];
                al[mt][2] = ALs[a0 + 4]; al[mt][3] = ALs[a1 + 4];
            }
            #pragma unroll
            for (int nt = 0; nt < 4; nt++) {
                int col = wn * 32 + nt * 8 + g;
                int b0 = (kt * 8 + r) * PB_STR + col;
                int b1 = (kt * 8 + r + 4) * PB_STR + col;
                bh2[nt][0] = BHs[b0]; bh2[nt][1] = BHs[b1];
                bl2[nt][0] = BLs[b0]; bl2[nt][1] = BLs[b1];
            }
            #pragma unroll
            for (int mt = 0; mt < 2; mt++)
                #pragma unroll
                for (int nt = 0; nt < 4; nt++) {
                    mma_bf16(acc[mt][nt], ah[mt], bh2[nt]);
                    mma_bf16(acc[mt][nt], ah[mt], bl2[nt]);
                    mma_bf16(acc[mt][nt], al[mt], bh2[nt]);
                }
        }
    }

    #pragma unroll
    for (int mt = 0; mt < 2; mt++) {
        int row0 = m0 + wm * 32 + mt * 16 + g;
        #pragma unroll
        for (int nt = 0; nt < 4; nt++) {
            int gn = n0 + wn * 32 + nt * 8 + 2 * r;
            float bia0 = bo[gn], bia1 = bo[gn + 1];
            *(float2*)&out[(size_t)row0 * DD + gn] =
                make_float2(acc[mt][nt][0] + bia0, acc[mt][nt][1] + bia1);
            *(float2*)&out[(size_t)(row0 + 8) * DD + gn] =
                make_float2(acc[mt][nt][2] + bia0, acc[mt][nt][3] + bia1);
        }
    }
}

// ---------------------------------------------------------------------------
extern "C" void kernel_launch(void* const* d_in, const int* in_sizes, int n_in,
                              void* d_out, int out_size)
{
    const float* x  = (const float*)d_in[0];
    const float* Wq = (const float*)d_in[1];
    const float* bq = (const float*)d_in[2];
    const float* Wk = (const float*)d_in[3];
    const float* bk = (const float*)d_in[4];
    const float* Wv = (const float*)d_in[5];
    const float* bv = (const float*)d_in[6];
    const float* Wo = (const float*)d_in[7];
    const float* bo = (const float*)d_in[8];

    float* out  = (float*)d_out;
    float* wptr = out + (size_t)BB * SS * DD;

    const int gemm_smem = 3 * PSTG * (int)sizeof(uint32_t);   // 113664
    const int attn_smem = (2*UQ_SZ + 2*SCH_SZ + 3*KBUF_SZ + 3*VBUF_SZ + 32 + 256)
                          * (int)sizeof(uint32_t);            // 225408

    cudaFuncSetAttribute(proj_bf16,    cudaFuncAttributeMaxDynamicSharedMemorySize, gemm_smem);
    cudaFuncSetAttribute(outproj_bf16, cudaFuncAttributeMaxDynamicSharedMemorySize, gemm_smem);
    cudaFuncSetAttribute(attn_bf16,    cudaFuncAttributeMaxDynamicSharedMemorySize, attn_smem);

    presplit<<<512, 256>>>(x, Wq, Wk, Wv, Wo);
    proj_bf16<<<dim3(MM/128, NQKV/128), 512, gemm_smem>>>(bq, bk, bv);
    attn_bf16<<<dim3(BH, SS/QROWS), 512, attn_smem>>>(wptr);
    outproj_bf16<<<dim3(MM/128, DD/128), 512, gemm_smem>>>(bo, out);
}